// round 15
// baseline (speedup 1.0000x reference)
#include <cuda_runtime.h>
#include <cstdint>
#include <math.h>

// ---------------- problem constants ----------------
constexpr int Bc  = 8;
constexpr int Tc  = 256;
constexpr int Cc  = 1024;
constexpr int QDc = 768;
constexpr int LQc = 24;
constexpr int Kc  = 4;
constexpr int NWc = 241;     // T - W + 1
constexpr int Sc  = 8;
constexpr int Hc  = 4;
constexpr int HDc = 256;     // C/H
constexpr int SLc = 964;     // NW*K
constexpr int LHc = LQc * Hc; // 96

constexpr int PRED_SZ = Bc * 2 * NWc;  // 3856

// ---------------- scratch (device globals; no allocation allowed) ----------------
__device__ __align__(16) float g_xpe   [Bc * Tc * Cc];
__device__ __align__(16) float g_qpe   [Bc * LQc * QDc];
__device__ __align__(16) float g_Wc    [Cc * Cc];
__device__ __align__(16) float g_qbias [Cc];
__device__ __align__(16) float g_qbv   [Cc];
__device__ __align__(16) float g_e1    [Bc * LQc * Cc];
__device__ __align__(16) float g_e2    [Bc * LQc * Cc];
__device__ __align__(16) float g_e2k   [Bc * LQc * Cc];
__device__ __align__(16) float g_F     [Bc * LQc * Cc];
__device__ __align__(16) float g_sim   [Bc * Tc * LQc];
__device__ __align__(16) float g_biasl [Bc * LQc];
__device__ __align__(16) float g_cnt   [Bc * LQc];
__device__ __align__(16) float g_P     [Bc * LHc * Cc];
__device__ __align__(16) float g_W2P   [Bc * LHc * Cc];
__device__ __align__(16) float g_bterm [Bc * LHc];
__device__ __align__(16) float g_bP    [Bc * LHc];
__device__ __align__(16) float g_sut   [Bc * Tc * LHc];
__device__ __align__(16) float g_wcoef [Bc * SLc * LHc];
__device__ __align__(16) float g_Amat  [Bc * LQc * Tc];
__device__ __align__(16) float g_tmp   [Bc * LQc * Cc];
__device__ __align__(16) float g_qsum  [Bc * LQc * Cc];
__device__ __align__(16) float g_VS    [Bc * LQc * Cc];
__device__ __align__(16) float g_VSo   [Bc * LHc * Cc];
__device__ __align__(16) float g_outb  [Bc * SLc * Cc];
__device__ __align__(16) float g_G     [Bc * Kc * LHc * Cc];
__device__ __align__(16) float g_bconst[Cc];
__device__ __align__(16) float g_hbuf  [Bc * NWc * Cc];
__device__ __align__(16) float g_mp    [Bc * Sc * Cc];

// ---------------- grouped GEMM descriptor ----------------
struct GDesc {
    const float* A; const float* B; float* C; const float* bias;
    int lda, ldb, ldc;
    long sA1, sA2, sB1, sB2, sC1, sC2;
    int M, N, K, bdiv;
    int transB, relu;
    float alpha;
    int tileStart, tilesPerBatch, tilesX;
    int mblk;           // if >0: C row gm -> (gm/mblk)*sMblk + (gm%mblk)*ldc
    long sMblk;
};
struct GPack { GDesc g[3]; int n; };

// ---------------- grouped GEMM: 64x64 tile, 128 threads, 8x4 microtile ----------------
__global__ void __launch_bounds__(128) ggemm_kernel(GPack pk)
{
    __shared__ float As[2][16][68];
    __shared__ float Bs[2][16][68];

    int id = blockIdx.x;
    int gi = 0;
    if (pk.n > 1 && id >= pk.g[1].tileStart) gi = 1;
    if (pk.n > 2 && id >= pk.g[2].tileStart) gi = 2;
    const GDesc& d = pk.g[gi];
    int local = id - d.tileStart;
    int z  = local / d.tilesPerBatch;
    int t  = local - z * d.tilesPerBatch;
    int by = t / d.tilesX;
    int bx = t - by * d.tilesX;
    int z1 = z / d.bdiv, z2 = z - z1 * d.bdiv;

    const float* A = d.A + z1 * d.sA1 + z2 * d.sA2;
    const float* B = d.B + z1 * d.sB1 + z2 * d.sB2;
    float*       C = d.C + z1 * d.sC1 + z2 * d.sC2;
    const int M = d.M, N = d.N, K = d.K;
    const int lda = d.lda, ldb = d.ldb, ldc = d.ldc;
    const bool TRANSB = d.transB;

    const int tid = threadIdx.x;        // 128 threads
    const int tx = tid & 15;
    const int trow = tid >> 4;
    const int rowBase = by * 64;
    const int colBase = bx * 64;

    float acc[8][4] = {};
    float sa[8];
    float sb[8];

    auto loadTiles = [&](int k0) {
#pragma unroll
        for (int i = 0; i < 8; i++) {
            int l = tid + i * 128;
            int m = l >> 4, kk = l & 15;
            int gm = rowBase + m;
            sa[i] = (gm < M) ? A[(long)gm * lda + k0 + kk] : 0.f;
        }
        if (TRANSB) {
            int n = tid >> 1, k8 = (tid & 1) * 8;
            int gn = colBase + n;
            if (gn < N) {
                float4 v0 = *(const float4*)(B + (long)gn * ldb + k0 + k8);
                float4 v1 = *(const float4*)(B + (long)gn * ldb + k0 + k8 + 4);
                sb[0] = v0.x; sb[1] = v0.y; sb[2] = v0.z; sb[3] = v0.w;
                sb[4] = v1.x; sb[5] = v1.y; sb[6] = v1.z; sb[7] = v1.w;
            } else {
#pragma unroll
                for (int j = 0; j < 8; j++) sb[j] = 0.f;
            }
        } else {
#pragma unroll
            for (int i = 0; i < 8; i++) {
                int l = tid + i * 128;
                int kk = l >> 6, n = l & 63;
                int gn = colBase + n;
                sb[i] = (gn < N) ? B[(long)(k0 + kk) * ldb + gn] : 0.f;
            }
        }
    };
    auto storeTiles = [&](int p) {
#pragma unroll
        for (int i = 0; i < 8; i++) {
            int l = tid + i * 128;
            int m = l >> 4, kk = l & 15;
            As[p][kk][m] = sa[i];
        }
        if (TRANSB) {
            int n = tid >> 1, k8 = (tid & 1) * 8;
#pragma unroll
            for (int j = 0; j < 8; j++) Bs[p][k8 + j][n] = sb[j];
        } else {
#pragma unroll
            for (int i = 0; i < 8; i++) {
                int l = tid + i * 128;
                int kk = l >> 6, n = l & 63;
                Bs[p][kk][n] = sb[i];
            }
        }
    };

    loadTiles(0);
    storeTiles(0);
    __syncthreads();

    int p = 0;
    for (int k0 = 0; k0 < K; k0 += 16) {
        const bool hasNext = (k0 + 16 < K);
        if (hasNext) loadTiles(k0 + 16);

#pragma unroll
        for (int kk = 0; kk < 16; kk++) {
            const float* arow = &As[p][kk][trow * 8];
            float4 a0 = *(const float4*)arow;
            float4 a1 = *(const float4*)(arow + 4);
            float4 b0 = *(const float4*)&Bs[p][kk][tx * 4];
            float ra[8] = {a0.x, a0.y, a0.z, a0.w, a1.x, a1.y, a1.z, a1.w};
            float rb[4] = {b0.x, b0.y, b0.z, b0.w};
#pragma unroll
            for (int i = 0; i < 8; i++)
#pragma unroll
                for (int j = 0; j < 4; j++)
                    acc[i][j] += ra[i] * rb[j];
        }
        if (hasNext) storeTiles(1 - p);
        __syncthreads();
        p ^= 1;
    }

#pragma unroll
    for (int i = 0; i < 8; i++) {
        int gm = rowBase + trow * 8 + i;
        if (gm >= M) continue;
        long rowOff;
        if (d.mblk > 0) rowOff = (long)(gm / d.mblk) * d.sMblk + (long)(gm % d.mblk) * ldc;
        else            rowOff = (long)gm * ldc;
        int gn0 = colBase + tx * 4;
#pragma unroll
        for (int j = 0; j < 4; j++) {
            int gn = gn0 + j;
            if (gn >= N) continue;
            float val = acc[i][j] * d.alpha + (d.bias ? d.bias[gn] : 0.f);
            if (d.relu) val = fmaxf(val, 0.f);
            C[rowOff + gn] = val;
        }
    }
}

// ---------------- singleton tiled GEMM: 64x64 tile, 128 threads, 8x4 microtile ------
// Optional epilogue rank-1 term: if rsc != nullptr, C += rsc[gm] * rvec[gn].
template<bool TRANSB, bool RELU>
__global__ void __launch_bounds__(128) gemm_kernel(
    const float* __restrict__ A, int lda, long sA1, long sA2,
    const float* __restrict__ B, int ldb, long sB1, long sB2,
    float* __restrict__ Cm, int ldc, long sC1, long sC2,
    int M, int N, int K, int bdiv,
    const float* __restrict__ bias, float alpha,
    const float* __restrict__ rsc, const float* __restrict__ rvec)
{
    __shared__ float As[2][16][68];
    __shared__ float Bs[2][16][68];

    const int z = blockIdx.z, z1 = z / bdiv, z2 = z % bdiv;
    A  += z1 * sA1 + z2 * sA2;
    B  += z1 * sB1 + z2 * sB2;
    Cm += z1 * sC1 + z2 * sC2;

    const int tid = threadIdx.x;        // 128 threads
    const int tx = tid & 15;
    const int trow = tid >> 4;
    const int rowBase = blockIdx.y * 64;
    const int colBase = blockIdx.x * 64;

    float acc[8][4] = {};
    float sa[8];
    float sb[8];

    auto loadTiles = [&](int k0) {
#pragma unroll
        for (int i = 0; i < 8; i++) {
            int l = tid + i * 128;
            int m = l >> 4, kk = l & 15;
            int gm = rowBase + m;
            sa[i] = (gm < M) ? A[(long)gm * lda + k0 + kk] : 0.f;
        }
        if (TRANSB) {
            int n = tid >> 1, k8 = (tid & 1) * 8;
            int gn = colBase + n;
            if (gn < N) {
                float4 v0 = *(const float4*)(B + (long)gn * ldb + k0 + k8);
                float4 v1 = *(const float4*)(B + (long)gn * ldb + k0 + k8 + 4);
                sb[0] = v0.x; sb[1] = v0.y; sb[2] = v0.z; sb[3] = v0.w;
                sb[4] = v1.x; sb[5] = v1.y; sb[6] = v1.z; sb[7] = v1.w;
            } else {
#pragma unroll
                for (int j = 0; j < 8; j++) sb[j] = 0.f;
            }
        } else {
#pragma unroll
            for (int i = 0; i < 8; i++) {
                int l = tid + i * 128;
                int kk = l >> 6, n = l & 63;
                int gn = colBase + n;
                sb[i] = (gn < N) ? B[(long)(k0 + kk) * ldb + gn] : 0.f;
            }
        }
    };
    auto storeTiles = [&](int p) {
#pragma unroll
        for (int i = 0; i < 8; i++) {
            int l = tid + i * 128;
            int m = l >> 4, kk = l & 15;
            As[p][kk][m] = sa[i];
        }
        if (TRANSB) {
            int n = tid >> 1, k8 = (tid & 1) * 8;
#pragma unroll
            for (int j = 0; j < 8; j++) Bs[p][k8 + j][n] = sb[j];
        } else {
#pragma unroll
            for (int i = 0; i < 8; i++) {
                int l = tid + i * 128;
                int kk = l >> 6, n = l & 63;
                Bs[p][kk][n] = sb[i];
            }
        }
    };

    loadTiles(0);
    storeTiles(0);
    __syncthreads();

    int p = 0;
    for (int k0 = 0; k0 < K; k0 += 16) {
        const bool hasNext = (k0 + 16 < K);
        if (hasNext) loadTiles(k0 + 16);

#pragma unroll
        for (int kk = 0; kk < 16; kk++) {
            const float* arow = &As[p][kk][trow * 8];
            float4 a0 = *(const float4*)arow;
            float4 a1 = *(const float4*)(arow + 4);
            float4 b0 = *(const float4*)&Bs[p][kk][tx * 4];
            float ra[8] = {a0.x, a0.y, a0.z, a0.w, a1.x, a1.y, a1.z, a1.w};
            float rb[4] = {b0.x, b0.y, b0.z, b0.w};
#pragma unroll
            for (int i = 0; i < 8; i++)
#pragma unroll
                for (int j = 0; j < 4; j++)
                    acc[i][j] += ra[i] * rb[j];
        }
        if (hasNext) storeTiles(1 - p);
        __syncthreads();
        p ^= 1;
    }

#pragma unroll
    for (int i = 0; i < 8; i++) {
        int gm = rowBase + trow * 8 + i;
        if (gm >= M) continue;
        float rs = rsc ? rsc[gm] : 0.f;
        int gn0 = colBase + tx * 4;
#pragma unroll
        for (int j = 0; j < 4; j++) {
            int gn = gn0 + j;
            if (gn >= N) continue;
            float val = acc[i][j] * alpha + (bias ? bias[gn] : 0.f);
            if (rsc) val += rs * rvec[gn];
            if (RELU) val = fmaxf(val, 0.f);
            Cm[(long)gm * ldc + gn] = val;
        }
    }
}

// ---------------- fused positional encodings (vis + query) ----------------
__global__ void pe2_kernel(const float* __restrict__ vis, const float* __restrict__ query,
                           float* __restrict__ xpe, float* __restrict__ qpe)
{
    const int n1 = Bc * Tc * Cc;
    const int n2 = Bc * LQc * QDc;
    int idx = blockIdx.x * blockDim.x + threadIdx.x;
    const float* src; float* dst; int local, L, D;
    if (idx < n1) { src = vis; dst = xpe; local = idx; L = Tc; D = Cc; }
    else if (idx < n1 + n2) { src = query; dst = qpe; local = idx - n1; L = LQc; D = QDc; }
    else return;
    int c = local % D;
    int pos = (local / D) % L;
    int i2 = (c >> 1) * 2;
    float freq = expf((float)i2 * (-logf(10000.f) / (float)D));
    float ang = (float)pos * freq;
    float pe = (c & 1) ? cosf(ang) : sinf(ang);
    dst[local] = src[local] + pe;
}

// ---------------- fused qbias + bconst (independent warp-dots) ----------------
__global__ void qb2_kernel(const float* __restrict__ w_v2, const float* __restrict__ b_v1,
                           const float* __restrict__ b_v2,
                           const float* __restrict__ w_p1, const float* __restrict__ b_out,
                           const float* __restrict__ b_p1,
                           float* __restrict__ qbias, float* __restrict__ bconst)
{
    int gw = (blockIdx.x * blockDim.x + threadIdx.x) >> 5;
    int lane = threadIdx.x & 31;
    if (gw < Cc) {
        const float* row = w_v2 + (long)gw * Cc;
        float s = 0.f;
        for (int i = lane; i < Cc; i += 32) s += row[i] * b_v1[i];
#pragma unroll
        for (int o = 16; o; o >>= 1) s += __shfl_down_sync(0xffffffff, s, o);
        if (lane == 0) qbias[gw] = s + b_v2[gw];
    } else if (gw < 2 * Cc) {
        int w = gw - Cc;
        const float* row = w_p1 + (long)w * (Kc * Cc);
        float s = 0.f;
        for (int i = lane; i < Kc * Cc; i += 32) s += row[i] * b_out[i & (Cc - 1)];
#pragma unroll
        for (int o = 16; o; o >>= 1) s += __shfl_down_sync(0xffffffff, s, o);
        if (lane == 0) bconst[w] = s + b_p1[w];
    }
}

// ---------------- qbv[c] = qbias . wv[c,:] + bv[c] ----------------
__global__ void qbv_kernel(const float* __restrict__ qbias, const float* __restrict__ wv,
                           const float* __restrict__ bv, float* __restrict__ qbv)
{
    int w = (blockIdx.x * blockDim.x + threadIdx.x) >> 5;
    int lane = threadIdx.x & 31;
    if (w >= Cc) return;
    const float* row = wv + (long)w * Cc;
    float s = 0.f;
    for (int i = lane; i < Cc; i += 32) s += row[i] * qbias[i];
#pragma unroll
    for (int o = 16; o; o >>= 1) s += __shfl_down_sync(0xffffffff, s, o);
    if (lane == 0) qbv[w] = s + bv[w];
}

// ---------------- fused warp-dots: biasl, bterm, bP ----------------
__global__ void dots_kernel(const float* __restrict__ e1, const float* __restrict__ b_v1,
                            const float* __restrict__ e2k, const float* __restrict__ b_in,
                            const float* __restrict__ P, const float* __restrict__ qbias,
                            float* __restrict__ biasl, float* __restrict__ bterm,
                            float* __restrict__ bP)
{
    int gw = (blockIdx.x * blockDim.x + threadIdx.x) >> 5;
    int lane = threadIdx.x & 31;
    if (gw < Bc * LQc) {
        const float* row = e1 + (long)gw * Cc;
        float s = 0.f;
        for (int i = lane; i < Cc; i += 32) s += row[i] * b_v1[i];
#pragma unroll
        for (int o = 16; o; o >>= 1) s += __shfl_down_sync(0xffffffff, s, o);
        if (lane == 0) biasl[gw] = s;
    } else if (gw < Bc * LQc + Bc * LHc) {
        int idx = gw - Bc * LQc;
        int b = idx / LHc, j = idx % LHc;
        int l = j / Hc, h = j % Hc;
        const float* e = e2k + ((long)b * LQc + l) * Cc + h * HDc;
        const float* bq = b_in + h * HDc;
        float s = 0.f;
        for (int i = lane; i < HDc; i += 32) s += bq[i] * e[i];
#pragma unroll
        for (int o = 16; o; o >>= 1) s += __shfl_down_sync(0xffffffff, s, o);
        if (lane == 0) bterm[idx] = s;
    } else if (gw < Bc * LQc + 2 * Bc * LHc) {
        int idx = gw - Bc * LQc - Bc * LHc;
        const float* row = P + (long)idx * Cc;
        float s = 0.f;
        for (int i = lane; i < Cc; i += 32) s += row[i] * qbias[i];
#pragma unroll
        for (int o = 16; o; o >>= 1) s += __shfl_down_sync(0xffffffff, s, o);
        if (lane == 0) bP[idx] = s;
    }
}

// ---------------- fused argmax + mode + Amat + cnt (per-batch block) ----------------
__global__ void amatcnt_kernel(const float* __restrict__ sim, const float* __restrict__ biasl,
                               float* __restrict__ Amat, float* __restrict__ cnt)
{
    const int b = blockIdx.x;
    const int tid = threadIdx.x;      // 256
    __shared__ float Ab[LQc * Tc];
    __shared__ int lab[Tc];
    for (int i = tid; i < LQc * Tc; i += 256) Ab[i] = 0.f;
    // argmax for t = tid (Tc == 256 == blockDim)
    {
        const float* p = sim + ((long)b * Tc + tid) * LQc;
        const float* bl = biasl + b * LQc;
        float best = -INFINITY; int bestl = 0;
#pragma unroll
        for (int l = 0; l < LQc; l++) {
            float v = p[l] + bl[l];
            if (v > best) { best = v; bestl = l; }
        }
        lab[tid] = bestl;
    }
    __syncthreads();
    for (int s = tid; s < SLc; s += 256) {
        int n = s >> 2, k = s & 3;
        int base = n + 4 * k;
        int labs[4] = {lab[base], lab[base + 1], lab[base + 2], lab[base + 3]};
        int bestl = LQc, bestc = 0;
#pragma unroll
        for (int j = 0; j < 4; j++) {
            int c = 0;
#pragma unroll
            for (int j2 = 0; j2 < 4; j2++) c += (labs[j2] == labs[j]);
            if (c > bestc || (c == bestc && labs[j] < bestl)) { bestc = c; bestl = labs[j]; }
        }
        float* p = &Ab[bestl * Tc + base];
        atomicAdd(p + 0, 0.25f);
        atomicAdd(p + 1, 0.25f);
        atomicAdd(p + 2, 0.25f);
        atomicAdd(p + 3, 0.25f);
    }
    __syncthreads();
    for (int i = tid; i < LQc * Tc; i += 256) Amat[(long)b * LQc * Tc + i] = Ab[i];
    int warp = tid >> 5, lane = tid & 31;
    for (int l = warp; l < LQc; l += 8) {
        float s = 0.f;
        for (int t = lane; t < Tc; t += 32) s += Ab[l * Tc + t];
#pragma unroll
        for (int o = 16; o; o >>= 1) s += __shfl_down_sync(0xffffffff, s, o);
        if (lane == 0) cnt[b * LQc + l] = s;
    }
}

// ---------------- tmp[b,l,c] = sum_t Amat[b,l,t] * xpe[b,t,c] ----------------
__global__ void tmp_kernel(const float* __restrict__ Amat, const float* __restrict__ xpe,
                           float* __restrict__ tmp)
{
    const int b = blockIdx.x >> 2;         // 8 batches x 4 column-chunks
    const int chunk = blockIdx.x & 3;
    const int tid = threadIdx.x;           // 256
    __shared__ float As[LQc * Tc];
    for (int i = tid; i < LQc * Tc; i += 256) As[i] = Amat[(long)b * LQc * Tc + i];
    __syncthreads();
    const int c = chunk * 256 + tid;
    float acc[LQc] = {};
    const float* xb = xpe + (long)b * Tc * Cc + c;
    for (int t = 0; t < Tc; t++) {
        float v = xb[(long)t * Cc];
#pragma unroll
        for (int l = 0; l < LQc; l++) acc[l] += As[l * Tc + t] * v;
    }
#pragma unroll
    for (int l = 0; l < LQc; l++)
        tmp[((long)b * LQc + l) * Cc + c] = acc[l];
}

// ---------------- softmax weights (with inline su pooling) ----------------
__global__ void attnw_kernel(const float* __restrict__ sut, const float* __restrict__ bterm,
                             const float* __restrict__ cnt, const float* __restrict__ bP,
                             float* __restrict__ wcoef)
{
    const int bq = blockIdx.x;          // b*SL + q
    const int b = bq / SLc;
    const int q = bq % SLc;
    const int tid = threadIdx.x;        // 128: warp = head
    const int h = tid >> 5, l = tid & 31;
    const bool act = (l < LQc);
    const int j = l * Hc + h;

    float c_l = act ? cnt[b * LQc + l] : 0.f;
    float val;
    if (act) {
        int n = q >> 2, k = q & 3;
        int t0 = n + 4 * k;
        const float* p = sut + ((long)b * Tc + t0) * LHc + j;
        float su = (0.25f * (p[0] + p[LHc] + p[2 * LHc] + p[3 * LHc])
                    + bP[b * LHc + j]) * 0.0625f;
        val = su + bterm[b * LHc + j] * (1.f / 16.f);
    } else val = -INFINITY;
    float mval = (act && c_l > 0.f) ? val : -INFINITY;
#pragma unroll
    for (int o = 16; o; o >>= 1) mval = fmaxf(mval, __shfl_xor_sync(0xffffffff, mval, o));
    float e = act ? expf(val - mval) : 0.f;
    float zz = c_l * e;
#pragma unroll
    for (int o = 16; o; o >>= 1) zz += __shfl_xor_sync(0xffffffff, zz, o);
    if (act) wcoef[(long)bq * LHc + j] = (c_l > 0.f) ? (e / zz) : 0.f;
}

// ---------------- segment max pooling ----------------
__global__ void segmax_kernel(const float* __restrict__ outb, const int* __restrict__ vid_len,
                              float* __restrict__ mp)
{
    int idx = blockIdx.x * blockDim.x + threadIdx.x;
    if (idx >= Bc * Sc * Cc) return;
    int c = idx % Cc;
    int s = (idx / Cc) % Sc;
    int b = idx / (Sc * Cc);
    int Lb = vid_len[b] * Kc;
    int st = (s * Lb) / Sc;
    int en = ((s + 1) * Lb + Sc - 1) / Sc;
    float m = -INFINITY;
    const float* p = outb + ((long)b * SLc) * Cc + c;
    for (int t = st; t < en; t++) m = fmaxf(m, p[(long)t * Cc]);
    mp[idx] = m;
}

// ---------------- fused heads: pred (blocks 0..Bc*NW-1) + st/en (last 128) --------
__global__ void heads_kernel(const float* __restrict__ h, const float* __restrict__ w_p2,
                             const float* __restrict__ b_p2,
                             const float* __restrict__ mp,
                             const float* __restrict__ w_st, const float* __restrict__ b_st,
                             const float* __restrict__ w_en, const float* __restrict__ b_en,
                             float* __restrict__ out)
{
    const int tid = threadIdx.x, lane = tid & 31, warp = tid >> 5;
    if (blockIdx.x < Bc * NWc) {
        const int bn = blockIdx.x;
        const float* hr = h + (long)bn * Cc;
        __shared__ float r0[8], r1[8];
        float s0 = 0.f, s1 = 0.f;
        for (int i = tid; i < Cc; i += 256) {
            float hv = hr[i];
            s0 += hv * w_p2[i];
            s1 += hv * w_p2[Cc + i];
        }
#pragma unroll
        for (int o = 16; o; o >>= 1) {
            s0 += __shfl_down_sync(0xffffffff, s0, o);
            s1 += __shfl_down_sync(0xffffffff, s1, o);
        }
        if (lane == 0) { r0[warp] = s0; r1[warp] = s1; }
        __syncthreads();
        if (tid == 0) {
            float t0 = 0.f, t1 = 0.f;
#pragma unroll
            for (int w = 0; w < 8; w++) { t0 += r0[w]; t1 += r1[w]; }
            int b = bn / NWc, n = bn % NWc;
            out[(long)b * 2 * NWc + n] = t0 + b_p2[0];
            out[(long)b * 2 * NWc + NWc + n] = t1 + b_p2[1];
        }
    } else {
        const int id = blockIdx.x - Bc * NWc;  // 0..127
        const int b = id >> 4;
        const int r = id & 15;
        const int which = r >> 3;
        const int i = r & 7;
        const float* wgt = (which ? w_en : w_st) + (long)i * (Cc * Sc);
        __shared__ float red[8];
        float s = 0.f;
        for (int j = tid; j < Cc * Sc; j += 256) {
            int cc = j / Sc, ss = j % Sc;
            s += mp[((long)b * Sc + ss) * Cc + cc] * wgt[j];
        }
#pragma unroll
        for (int o = 16; o; o >>= 1) s += __shfl_down_sync(0xffffffff, s, o);
        if (lane == 0) red[warp] = s;
        __syncthreads();
        if (tid == 0) {
            float t = 0.f;
#pragma unroll
            for (int w = 0; w < 8; w++) t += red[w];
            float bias = (which ? b_en : b_st)[i];
            out[PRED_SZ + which * (Bc * Sc) + b * Sc + i] = t + bias;
        }
    }
}

// ---------------- host helpers ----------------
static inline dim3 tg(int M, int N, int batch) {
    return dim3((N + 63) / 64, (M + 63) / 64, batch);
}

static GDesc mk(const float* A, int lda, long sA1, long sA2,
                const float* B, int ldb, long sB1, long sB2,
                float* C, int ldc, long sC1, long sC2,
                int M, int N, int K, int bdiv, const float* bias, float alpha,
                int transB, int relu, int batch, int& cursor,
                int mblk = 0, long sMblk = 0)
{
    GDesc d;
    d.A = A; d.B = B; d.C = C; d.bias = bias;
    d.lda = lda; d.ldb = ldb; d.ldc = ldc;
    d.sA1 = sA1; d.sA2 = sA2; d.sB1 = sB1; d.sB2 = sB2; d.sC1 = sC1; d.sC2 = sC2;
    d.M = M; d.N = N; d.K = K; d.bdiv = bdiv;
    d.transB = transB; d.relu = relu; d.alpha = alpha;
    d.tilesX = (N + 63) / 64;
    int tilesY = (M + 63) / 64;
    d.tilesPerBatch = d.tilesX * tilesY;
    d.tileStart = cursor;
    d.mblk = mblk; d.sMblk = sMblk;
    cursor += d.tilesPerBatch * batch;
    return d;
}

extern "C" void kernel_launch(void* const* d_in, const int* in_sizes, int n_in,
                              void* d_out, int out_size)
{
    const float* vis   = (const float*)d_in[0];
    const float* query = (const float*)d_in[1];
    const int*   vlen  = (const int*)  d_in[2];
    const float* w_v1  = (const float*)d_in[3];
    const float* b_v1  = (const float*)d_in[4];
    const float* w_v2  = (const float*)d_in[5];
    const float* b_v2  = (const float*)d_in[6];
    const float* w_s1  = (const float*)d_in[7];
    const float* b_s1  = (const float*)d_in[8];
    const float* w_s2  = (const float*)d_in[9];
    const float* b_s2  = (const float*)d_in[10];
    const float* w_in  = (const float*)d_in[11];
    const float* b_in  = (const float*)d_in[12];
    const float* w_out = (const float*)d_in[13];
    const float* b_out = (const float*)d_in[14];
    const float* w_p1  = (const float*)d_in[15];
    const float* b_p1  = (const float*)d_in[16];
    const float* w_p2  = (const float*)d_in[17];
    const float* b_p2  = (const float*)d_in[18];
    const float* w_st  = (const float*)d_in[19];
    const float* b_st  = (const float*)d_in[20];
    const float* w_en  = (const float*)d_in[21];
    const float* b_en  = (const float*)d_in[22];
    float* out = (float*)d_out;

    float *xpe, *qpe, *Wc, *qbias, *qbv, *e1, *e2, *e2k, *F, *sim, *biasl,
          *cnt, *P, *W2P, *bterm, *bP, *sut, *wcoef, *Amat, *tmp,
          *qsum, *VS, *VSo, *outb, *G, *bconst, *hbuf, *mp;
    cudaGetSymbolAddress((void**)&xpe,   g_xpe);
    cudaGetSymbolAddress((void**)&qpe,   g_qpe);
    cudaGetSymbolAddress((void**)&Wc,    g_Wc);
    cudaGetSymbolAddress((void**)&qbias, g_qbias);
    cudaGetSymbolAddress((void**)&qbv,   g_qbv);
    cudaGetSymbolAddress((void**)&e1,    g_e1);
    cudaGetSymbolAddress((void**)&e2,    g_e2);
    cudaGetSymbolAddress((void**)&e2k,   g_e2k);
    cudaGetSymbolAddress((void**)&F,     g_F);
    cudaGetSymbolAddress((void**)&sim,   g_sim);
    cudaGetSymbolAddress((void**)&biasl, g_biasl);
    cudaGetSymbolAddress((void**)&cnt,   g_cnt);
    cudaGetSymbolAddress((void**)&P,     g_P);
    cudaGetSymbolAddress((void**)&W2P,   g_W2P);
    cudaGetSymbolAddress((void**)&bterm, g_bterm);
    cudaGetSymbolAddress((void**)&bP,    g_bP);
    cudaGetSymbolAddress((void**)&sut,   g_sut);
    cudaGetSymbolAddress((void**)&wcoef, g_wcoef);
    cudaGetSymbolAddress((void**)&Amat,  g_Amat);
    cudaGetSymbolAddress((void**)&tmp,   g_tmp);
    cudaGetSymbolAddress((void**)&qsum,  g_qsum);
    cudaGetSymbolAddress((void**)&VS,    g_VS);
    cudaGetSymbolAddress((void**)&VSo,   g_VSo);
    cudaGetSymbolAddress((void**)&outb,  g_outb);
    cudaGetSymbolAddress((void**)&G,     g_G);
    cudaGetSymbolAddress((void**)&bconst,g_bconst);
    cudaGetSymbolAddress((void**)&hbuf,  g_hbuf);
    cudaGetSymbolAddress((void**)&mp,    g_mp);

    // 1. fused positional encodings
    {
        int n = Bc * Tc * Cc + Bc * LQc * QDc;
        pe2_kernel<<<(n + 255) / 256, 256>>>(vis, query, xpe, qpe);
    }
    // 2. fused qbias + bconst; then qbv
    qb2_kernel<<<(2 * Cc * 32 + 255) / 256, 256>>>(w_v2, b_v1, b_v2,
                                                   w_p1, b_out, b_p1, qbias, bconst);
    qbv_kernel<<<(Cc * 32 + 255) / 256, 256>>>(qbias, w_in + 2L * Cc * Cc, b_in + 2 * Cc, qbv);

    // 3. G1: [Wc, e1, e2]
    {
        int cur = 0;
        GPack pk; pk.n = 3;
        pk.g[0] = mk(w_v2, Cc, 0, 0, w_v1, Cc, 0, 0, Wc, Cc, 0, 0,
                     Cc, Cc, Cc, 1, nullptr, 1.f, 0, 0, 1, cur);
        pk.g[1] = mk(qpe, QDc, 0, 0, w_s1, QDc, 0, 0, e1, Cc, 0, 0,
                     Bc * LQc, Cc, QDc, 1, b_s1, 1.f, 1, 0, 1, cur);
        pk.g[2] = mk(qpe, QDc, 0, 0, w_s2, QDc, 0, 0, e2, Cc, 0, 0,
                     Bc * LQc, Cc, QDc, 1, b_s2, 1.f, 1, 0, 1, cur);
        ggemm_kernel<<<cur, 128>>>(pk);
    }

    // 4. G2: [F = e1 @ w_v1 (NN), e2k = e2 @ wk^T + bk (TB)]
    {
        int cur = 0;
        GPack pk; pk.n = 2;
        pk.g[0] = mk(e1, Cc, 0, 0, w_v1, Cc, 0, 0, F, Cc, 0, 0,
                     Bc * LQc, Cc, Cc, 1, nullptr, 1.f, 0, 0, 1, cur);
        pk.g[1] = mk(e2, Cc, 0, 0, w_in + (long)Cc * Cc, Cc, 0, 0, e2k, Cc, 0, 0,
                     Bc * LQc, Cc, Cc, 1, b_in + Cc, 1.f, 1, 0, 1, cur);
        ggemm_kernel<<<cur, 128>>>(pk);
    }

    // 5. G3: [sim = xpe @ F^T (TB, batch 8), P = e2k_h @ wq_h (NN, batch 4)]
    {
        int cur = 0;
        GPack pk; pk.n = 2;
        pk.g[0] = mk(xpe, Cc, (long)Tc * Cc, 0, F, Cc, (long)LQc * Cc, 0,
                     sim, LQc, (long)Tc * LQc, 0,
                     Tc, LQc, Cc, 1, nullptr, 1.f, 1, 0, Bc, cur);
        pk.g[1] = mk(e2k, Cc, (long)HDc, 0, w_in, Cc, (long)HDc * Cc, 0,
                     P, Hc * Cc, (long)Cc, 0,
                     Bc * LQc, Cc, HDc, 1, nullptr, 1.f, 0, 0, Hc, cur);
        ggemm_kernel<<<cur, 128>>>(pk);
    }

    // 6. fused dots (biasl, bterm, bP)
    {
        int warps = Bc * LQc + 2 * Bc * LHc;   // 1728
        dots_kernel<<<(warps * 32 + 255) / 256, 256>>>(e1, b_v1, e2k, b_in, P, qbias,
                                                       biasl, bterm, bP);
    }

    // 7. fused argmax + mode + Amat + cnt ; tmp
    amatcnt_kernel<<<Bc, 256>>>(sim, biasl, Amat, cnt);
    tmp_kernel<<<Bc * 4, 256>>>(Amat, xpe, tmp);

    // 8. W2P = P_flat(768x1024) @ Wc (NN, batch 1, zero M-waste)
    gemm_kernel<false, false><<<tg(Bc * LHc, Cc, 1), 128>>>(
        P, Cc, 0, 0, Wc, Cc, 0, 0, W2P, Cc, 0, 0,
        Bc * LHc, Cc, Cc, 1, nullptr, 1.f, nullptr, nullptr);

    // 9. G5: [sut = xpe @ W2P^T (TB, batch 8), qsum = tmp @ Wc^T (TB)]
    {
        int cur = 0;
        GPack pk; pk.n = 2;
        pk.g[0] = mk(xpe, Cc, (long)Tc * Cc, 0, W2P, Cc, (long)LHc * Cc, 0,
                     sut, LHc, (long)Tc * LHc, 0,
                     Tc, LHc, Cc, 1, nullptr, 1.f, 1, 0, Bc, cur);
        pk.g[1] = mk(tmp, Cc, 0, 0, Wc, Cc, 0, 0, qsum, Cc, 0, 0,
                     Bc * LQc, Cc, Cc, 1, nullptr, 1.f, 1, 0, 1, cur);
        ggemm_kernel<<<cur, 128>>>(pk);
    }

    // 10. attnw (inline pooling) -> wcoef
    attnw_kernel<<<Bc * SLc, 128>>>(sut, bterm, cnt, bP, wcoef);

    // 11. VS = qsum @ wv^T + cnt[row]*qbv[col] (fused epilogue) ; VSo (TB batch 4)
    gemm_kernel<true, false><<<tg(Bc * LQc, Cc, 1), 128>>>(
        qsum, Cc, 0, 0, w_in + 2L * Cc * Cc, Cc, 0, 0, VS, Cc, 0, 0,
        Bc * LQc, Cc, Cc, 1, nullptr, 1.f, cnt, qbv);
    gemm_kernel<true, false><<<tg(Bc * LQc, Cc, Hc), 128>>>(
        VS, Cc, (long)HDc, 0,
        w_out, Cc, (long)HDc, 0,
        VSo, Hc * Cc, (long)Cc, 0,
        Bc * LQc, Cc, HDc, 1, nullptr, 1.f, nullptr, nullptr);

    // 12. G6: [G flattened M=768 batch j=4 (zero waste, remapped C), outb]
    {
        int cur = 0;
        GPack pk; pk.n = 2;
        // G: A = VSo_flat (768x1024, j-independent); B = w_p1 + j*1024 (TB, ldb=4096)
        // C row m=(b*96+r) -> b*(384*1024) [via mblk remap] + j*(96*1024) [via sC1] + r*1024
        pk.g[0] = mk(VSo, Cc, 0, 0,
                     w_p1, Kc * Cc, (long)Cc, 0,
                     G, Cc, (long)LHc * Cc, 0,
                     Bc * LHc, Cc, Cc, 1, nullptr, 1.f, 1, 0, Kc, cur,
                     LHc, (long)Kc * LHc * Cc);
        pk.g[1] = mk(wcoef, LHc, (long)SLc * LHc, 0,
                     VSo, Cc, (long)LHc * Cc, 0,
                     outb, Cc, (long)SLc * Cc, 0,
                     SLc, Cc, LHc, 1, b_out, 1.f, 0, 0, Bc, cur);
        ggemm_kernel<<<cur, 128>>>(pk);
    }

    // 13. hbuf = relu(wcoef_blocked(241x384) @ Gstack[b](384x1024) + bconst)
    gemm_kernel<false, true><<<tg(NWc, Cc, Bc), 128>>>(
        wcoef, Kc * LHc, (long)SLc * LHc, 0,
        G, Cc, (long)Kc * LHc * Cc, 0,
        hbuf, Cc, (long)NWc * Cc, 0,
        NWc, Cc, Kc * LHc, 1, bconst, 1.f, nullptr, nullptr);

    // 14. segmax ; fused heads (pred + st/en)
    segmax_kernel<<<(Bc * Sc * Cc + 255) / 256, 256>>>(outb, vlen, mp);
    heads_kernel<<<Bc * NWc + 128, 256>>>(hbuf, w_p2, b_p2, mp,
                                          w_st, b_st, w_en, b_en, out);
}

// round 16
// speedup vs baseline: 1.1264x; 1.1264x over previous
#include <cuda_runtime.h>
#include <cstdint>
#include <math.h>

// ---------------- problem constants ----------------
constexpr int Bc  = 8;
constexpr int Tc  = 256;
constexpr int Cc  = 1024;
constexpr int QDc = 768;
constexpr int LQc = 24;
constexpr int Kc  = 4;
constexpr int NWc = 241;     // T - W + 1
constexpr int Sc  = 8;
constexpr int Hc  = 4;
constexpr int HDc = 256;     // C/H
constexpr int SLc = 964;     // NW*K
constexpr int LHc = LQc * Hc; // 96

constexpr int PRED_SZ = Bc * 2 * NWc;  // 3856

// ---------------- scratch (device globals; no allocation allowed) ----------------
__device__ __align__(16) float g_xpe   [Bc * Tc * Cc];
__device__ __align__(16) float g_qpe   [Bc * LQc * QDc];
__device__ __align__(16) float g_Wc    [Cc * Cc];
__device__ __align__(16) float g_qbias [Cc];
__device__ __align__(16) float g_qbv   [Cc];
__device__ __align__(16) float g_e1    [Bc * LQc * Cc];
__device__ __align__(16) float g_e2    [Bc * LQc * Cc];
__device__ __align__(16) float g_e2k   [Bc * LQc * Cc];
__device__ __align__(16) float g_F     [Bc * LQc * Cc];
__device__ __align__(16) float g_sim   [Bc * Tc * LQc];
__device__ __align__(16) float g_biasl [Bc * LQc];
__device__ __align__(16) float g_cnt   [Bc * LQc];
__device__ __align__(16) float g_P     [Bc * LHc * Cc];
__device__ __align__(16) float g_W2P   [Bc * LHc * Cc];
__device__ __align__(16) float g_bterm [Bc * LHc];
__device__ __align__(16) float g_bP    [Bc * LHc];
__device__ __align__(16) float g_sut   [Bc * Tc * LHc];
__device__ __align__(16) float g_wcoef [Bc * SLc * LHc];
__device__ __align__(16) float g_Amat  [Bc * LQc * Tc];
__device__ __align__(16) float g_tmp   [Bc * LQc * Cc];
__device__ __align__(16) float g_qsum  [Bc * LQc * Cc];
__device__ __align__(16) float g_VS    [Bc * LQc * Cc];
__device__ __align__(16) float g_VSo   [Bc * LHc * Cc];
__device__ __align__(16) float g_outb  [Bc * SLc * Cc];
__device__ __align__(16) float g_G     [Bc * Kc * LHc * Cc];
__device__ __align__(16) float g_bconst[Cc];
__device__ __align__(16) float g_hbuf  [Bc * NWc * Cc];
__device__ __align__(16) float g_mp    [Bc * Sc * Cc];

// ---------------- grouped GEMM descriptor ----------------
struct GDesc {
    const float* A; const float* B; float* C; const float* bias;
    int lda, ldb, ldc;
    long sA1, sA2, sB1, sB2, sC1, sC2;
    int M, N, K, bdiv;
    int transB, relu;
    float alpha;
    int tileStart, tilesPerBatch, tilesX;
};
struct GPack { GDesc g[3]; int n; };

// ---------------- grouped GEMM: 64x64 tile, 128 threads, 8x4 microtile ----------------
__global__ void __launch_bounds__(128) ggemm_kernel(GPack pk)
{
    __shared__ float As[2][16][68];
    __shared__ float Bs[2][16][68];

    int id = blockIdx.x;
    int gi = 0;
    if (pk.n > 1 && id >= pk.g[1].tileStart) gi = 1;
    if (pk.n > 2 && id >= pk.g[2].tileStart) gi = 2;
    const GDesc& d = pk.g[gi];
    int local = id - d.tileStart;
    int z  = local / d.tilesPerBatch;
    int t  = local - z * d.tilesPerBatch;
    int by = t / d.tilesX;
    int bx = t - by * d.tilesX;
    int z1 = z / d.bdiv, z2 = z - z1 * d.bdiv;

    const float* A = d.A + z1 * d.sA1 + z2 * d.sA2;
    const float* B = d.B + z1 * d.sB1 + z2 * d.sB2;
    float*       C = d.C + z1 * d.sC1 + z2 * d.sC2;
    const int M = d.M, N = d.N, K = d.K;
    const int lda = d.lda, ldb = d.ldb, ldc = d.ldc;
    const bool TRANSB = d.transB;

    const int tid = threadIdx.x;        // 128 threads
    const int tx = tid & 15;
    const int trow = tid >> 4;
    const int rowBase = by * 64;
    const int colBase = bx * 64;

    float acc[8][4] = {};
    float sa[8];
    float sb[8];

    auto loadTiles = [&](int k0) {
#pragma unroll
        for (int i = 0; i < 8; i++) {
            int l = tid + i * 128;
            int m = l >> 4, kk = l & 15;
            int gm = rowBase + m;
            sa[i] = (gm < M) ? A[(long)gm * lda + k0 + kk] : 0.f;
        }
        if (TRANSB) {
            int n = tid >> 1, k8 = (tid & 1) * 8;
            int gn = colBase + n;
            if (gn < N) {
                float4 v0 = *(const float4*)(B + (long)gn * ldb + k0 + k8);
                float4 v1 = *(const float4*)(B + (long)gn * ldb + k0 + k8 + 4);
                sb[0] = v0.x; sb[1] = v0.y; sb[2] = v0.z; sb[3] = v0.w;
                sb[4] = v1.x; sb[5] = v1.y; sb[6] = v1.z; sb[7] = v1.w;
            } else {
#pragma unroll
                for (int j = 0; j < 8; j++) sb[j] = 0.f;
            }
        } else {
#pragma unroll
            for (int i = 0; i < 8; i++) {
                int l = tid + i * 128;
                int kk = l >> 6, n = l & 63;
                int gn = colBase + n;
                sb[i] = (gn < N) ? B[(long)(k0 + kk) * ldb + gn] : 0.f;
            }
        }
    };
    auto storeTiles = [&](int p) {
#pragma unroll
        for (int i = 0; i < 8; i++) {
            int l = tid + i * 128;
            int m = l >> 4, kk = l & 15;
            As[p][kk][m] = sa[i];
        }
        if (TRANSB) {
            int n = tid >> 1, k8 = (tid & 1) * 8;
#pragma unroll
            for (int j = 0; j < 8; j++) Bs[p][k8 + j][n] = sb[j];
        } else {
#pragma unroll
            for (int i = 0; i < 8; i++) {
                int l = tid + i * 128;
                int kk = l >> 6, n = l & 63;
                Bs[p][kk][n] = sb[i];
            }
        }
    };

    loadTiles(0);
    storeTiles(0);
    __syncthreads();

    int p = 0;
    for (int k0 = 0; k0 < K; k0 += 16) {
        const bool hasNext = (k0 + 16 < K);
        if (hasNext) loadTiles(k0 + 16);

#pragma unroll
        for (int kk = 0; kk < 16; kk++) {
            const float* arow = &As[p][kk][trow * 8];
            float4 a0 = *(const float4*)arow;
            float4 a1 = *(const float4*)(arow + 4);
            float4 b0 = *(const float4*)&Bs[p][kk][tx * 4];
            float ra[8] = {a0.x, a0.y, a0.z, a0.w, a1.x, a1.y, a1.z, a1.w};
            float rb[4] = {b0.x, b0.y, b0.z, b0.w};
#pragma unroll
            for (int i = 0; i < 8; i++)
#pragma unroll
                for (int j = 0; j < 4; j++)
                    acc[i][j] += ra[i] * rb[j];
        }
        if (hasNext) storeTiles(1 - p);
        __syncthreads();
        p ^= 1;
    }

#pragma unroll
    for (int i = 0; i < 8; i++) {
        int gm = rowBase + trow * 8 + i;
        if (gm >= M) continue;
        int gn0 = colBase + tx * 4;
#pragma unroll
        for (int j = 0; j < 4; j++) {
            int gn = gn0 + j;
            if (gn >= N) continue;
            float val = acc[i][j] * d.alpha + (d.bias ? d.bias[gn] : 0.f);
            if (d.relu) val = fmaxf(val, 0.f);
            C[(long)gm * ldc + gn] = val;
        }
    }
}

// ---------------- singleton tiled GEMM: 64x64 tile, 128 threads, 8x4 microtile ------
// Optional epilogue rank-1 term: if rsc != nullptr, C += rsc[gm] * rvec[gn].
template<bool TRANSB, bool RELU>
__global__ void __launch_bounds__(128) gemm_kernel(
    const float* __restrict__ A, int lda, long sA1, long sA2,
    const float* __restrict__ B, int ldb, long sB1, long sB2,
    float* __restrict__ Cm, int ldc, long sC1, long sC2,
    int M, int N, int K, int bdiv,
    const float* __restrict__ bias, float alpha,
    const float* __restrict__ rsc, const float* __restrict__ rvec)
{
    __shared__ float As[2][16][68];
    __shared__ float Bs[2][16][68];

    const int z = blockIdx.z, z1 = z / bdiv, z2 = z % bdiv;
    A  += z1 * sA1 + z2 * sA2;
    B  += z1 * sB1 + z2 * sB2;
    Cm += z1 * sC1 + z2 * sC2;

    const int tid = threadIdx.x;        // 128 threads
    const int tx = tid & 15;
    const int trow = tid >> 4;
    const int rowBase = blockIdx.y * 64;
    const int colBase = blockIdx.x * 64;

    float acc[8][4] = {};
    float sa[8];
    float sb[8];

    auto loadTiles = [&](int k0) {
#pragma unroll
        for (int i = 0; i < 8; i++) {
            int l = tid + i * 128;
            int m = l >> 4, kk = l & 15;
            int gm = rowBase + m;
            sa[i] = (gm < M) ? A[(long)gm * lda + k0 + kk] : 0.f;
        }
        if (TRANSB) {
            int n = tid >> 1, k8 = (tid & 1) * 8;
            int gn = colBase + n;
            if (gn < N) {
                float4 v0 = *(const float4*)(B + (long)gn * ldb + k0 + k8);
                float4 v1 = *(const float4*)(B + (long)gn * ldb + k0 + k8 + 4);
                sb[0] = v0.x; sb[1] = v0.y; sb[2] = v0.z; sb[3] = v0.w;
                sb[4] = v1.x; sb[5] = v1.y; sb[6] = v1.z; sb[7] = v1.w;
            } else {
#pragma unroll
                for (int j = 0; j < 8; j++) sb[j] = 0.f;
            }
        } else {
#pragma unroll
            for (int i = 0; i < 8; i++) {
                int l = tid + i * 128;
                int kk = l >> 6, n = l & 63;
                int gn = colBase + n;
                sb[i] = (gn < N) ? B[(long)(k0 + kk) * ldb + gn] : 0.f;
            }
        }
    };
    auto storeTiles = [&](int p) {
#pragma unroll
        for (int i = 0; i < 8; i++) {
            int l = tid + i * 128;
            int m = l >> 4, kk = l & 15;
            As[p][kk][m] = sa[i];
        }
        if (TRANSB) {
            int n = tid >> 1, k8 = (tid & 1) * 8;
#pragma unroll
            for (int j = 0; j < 8; j++) Bs[p][k8 + j][n] = sb[j];
        } else {
#pragma unroll
            for (int i = 0; i < 8; i++) {
                int l = tid + i * 128;
                int kk = l >> 6, n = l & 63;
                Bs[p][kk][n] = sb[i];
            }
        }
    };

    loadTiles(0);
    storeTiles(0);
    __syncthreads();

    int p = 0;
    for (int k0 = 0; k0 < K; k0 += 16) {
        const bool hasNext = (k0 + 16 < K);
        if (hasNext) loadTiles(k0 + 16);

#pragma unroll
        for (int kk = 0; kk < 16; kk++) {
            const float* arow = &As[p][kk][trow * 8];
            float4 a0 = *(const float4*)arow;
            float4 a1 = *(const float4*)(arow + 4);
            float4 b0 = *(const float4*)&Bs[p][kk][tx * 4];
            float ra[8] = {a0.x, a0.y, a0.z, a0.w, a1.x, a1.y, a1.z, a1.w};
            float rb[4] = {b0.x, b0.y, b0.z, b0.w};
#pragma unroll
            for (int i = 0; i < 8; i++)
#pragma unroll
                for (int j = 0; j < 4; j++)
                    acc[i][j] += ra[i] * rb[j];
        }
        if (hasNext) storeTiles(1 - p);
        __syncthreads();
        p ^= 1;
    }

#pragma unroll
    for (int i = 0; i < 8; i++) {
        int gm = rowBase + trow * 8 + i;
        if (gm >= M) continue;
        float rs = rsc ? rsc[gm] : 0.f;
        int gn0 = colBase + tx * 4;
#pragma unroll
        for (int j = 0; j < 4; j++) {
            int gn = gn0 + j;
            if (gn >= N) continue;
            float val = acc[i][j] * alpha + (bias ? bias[gn] : 0.f);
            if (rsc) val += rs * rvec[gn];
            if (RELU) val = fmaxf(val, 0.f);
            Cm[(long)gm * ldc + gn] = val;
        }
    }
}

// ---------------- fused positional encodings (vis + query) ----------------
__global__ void pe2_kernel(const float* __restrict__ vis, const float* __restrict__ query,
                           float* __restrict__ xpe, float* __restrict__ qpe)
{
    const int n1 = Bc * Tc * Cc;
    const int n2 = Bc * LQc * QDc;
    int idx = blockIdx.x * blockDim.x + threadIdx.x;
    const float* src; float* dst; int local, L, D;
    if (idx < n1) { src = vis; dst = xpe; local = idx; L = Tc; D = Cc; }
    else if (idx < n1 + n2) { src = query; dst = qpe; local = idx - n1; L = LQc; D = QDc; }
    else return;
    int c = local % D;
    int pos = (local / D) % L;
    int i2 = (c >> 1) * 2;
    float freq = expf((float)i2 * (-logf(10000.f) / (float)D));
    float ang = (float)pos * freq;
    float pe = (c & 1) ? cosf(ang) : sinf(ang);
    dst[local] = src[local] + pe;
}

// ---------------- fused qbias + bconst (independent warp-dots) ----------------
__global__ void qb2_kernel(const float* __restrict__ w_v2, const float* __restrict__ b_v1,
                           const float* __restrict__ b_v2,
                           const float* __restrict__ w_p1, const float* __restrict__ b_out,
                           const float* __restrict__ b_p1,
                           float* __restrict__ qbias, float* __restrict__ bconst)
{
    int gw = (blockIdx.x * blockDim.x + threadIdx.x) >> 5;
    int lane = threadIdx.x & 31;
    if (gw < Cc) {
        const float* row = w_v2 + (long)gw * Cc;
        float s = 0.f;
        for (int i = lane; i < Cc; i += 32) s += row[i] * b_v1[i];
#pragma unroll
        for (int o = 16; o; o >>= 1) s += __shfl_down_sync(0xffffffff, s, o);
        if (lane == 0) qbias[gw] = s + b_v2[gw];
    } else if (gw < 2 * Cc) {
        int w = gw - Cc;
        const float* row = w_p1 + (long)w * (Kc * Cc);
        float s = 0.f;
        for (int i = lane; i < Kc * Cc; i += 32) s += row[i] * b_out[i & (Cc - 1)];
#pragma unroll
        for (int o = 16; o; o >>= 1) s += __shfl_down_sync(0xffffffff, s, o);
        if (lane == 0) bconst[w] = s + b_p1[w];
    }
}

// ---------------- qbv[c] = qbias . wv[c,:] + bv[c] ----------------
__global__ void qbv_kernel(const float* __restrict__ qbias, const float* __restrict__ wv,
                           const float* __restrict__ bv, float* __restrict__ qbv)
{
    int w = (blockIdx.x * blockDim.x + threadIdx.x) >> 5;
    int lane = threadIdx.x & 31;
    if (w >= Cc) return;
    const float* row = wv + (long)w * Cc;
    float s = 0.f;
    for (int i = lane; i < Cc; i += 32) s += row[i] * qbias[i];
#pragma unroll
    for (int o = 16; o; o >>= 1) s += __shfl_down_sync(0xffffffff, s, o);
    if (lane == 0) qbv[w] = s + bv[w];
}

// ---------------- fused warp-dots: biasl, bterm, bP ----------------
__global__ void dots_kernel(const float* __restrict__ e1, const float* __restrict__ b_v1,
                            const float* __restrict__ e2k, const float* __restrict__ b_in,
                            const float* __restrict__ P, const float* __restrict__ qbias,
                            float* __restrict__ biasl, float* __restrict__ bterm,
                            float* __restrict__ bP)
{
    int gw = (blockIdx.x * blockDim.x + threadIdx.x) >> 5;
    int lane = threadIdx.x & 31;
    if (gw < Bc * LQc) {
        const float* row = e1 + (long)gw * Cc;
        float s = 0.f;
        for (int i = lane; i < Cc; i += 32) s += row[i] * b_v1[i];
#pragma unroll
        for (int o = 16; o; o >>= 1) s += __shfl_down_sync(0xffffffff, s, o);
        if (lane == 0) biasl[gw] = s;
    } else if (gw < Bc * LQc + Bc * LHc) {
        int idx = gw - Bc * LQc;
        int b = idx / LHc, j = idx % LHc;
        int l = j / Hc, h = j % Hc;
        const float* e = e2k + ((long)b * LQc + l) * Cc + h * HDc;
        const float* bq = b_in + h * HDc;
        float s = 0.f;
        for (int i = lane; i < HDc; i += 32) s += bq[i] * e[i];
#pragma unroll
        for (int o = 16; o; o >>= 1) s += __shfl_down_sync(0xffffffff, s, o);
        if (lane == 0) bterm[idx] = s;
    } else if (gw < Bc * LQc + 2 * Bc * LHc) {
        int idx = gw - Bc * LQc - Bc * LHc;
        const float* row = P + (long)idx * Cc;
        float s = 0.f;
        for (int i = lane; i < Cc; i += 32) s += row[i] * qbias[i];
#pragma unroll
        for (int o = 16; o; o >>= 1) s += __shfl_down_sync(0xffffffff, s, o);
        if (lane == 0) bP[idx] = s;
    }
}

// ---------------- fused argmax + mode + Amat + cnt (per-batch block) ----------------
__global__ void amatcnt_kernel(const float* __restrict__ sim, const float* __restrict__ biasl,
                               float* __restrict__ Amat, float* __restrict__ cnt)
{
    const int b = blockIdx.x;
    const int tid = threadIdx.x;      // 256
    __shared__ float Ab[LQc * Tc];
    __shared__ int lab[Tc];
    for (int i = tid; i < LQc * Tc; i += 256) Ab[i] = 0.f;
    // argmax for t = tid (Tc == 256 == blockDim)
    {
        const float* p = sim + ((long)b * Tc + tid) * LQc;
        const float* bl = biasl + b * LQc;
        float best = -INFINITY; int bestl = 0;
#pragma unroll
        for (int l = 0; l < LQc; l++) {
            float v = p[l] + bl[l];
            if (v > best) { best = v; bestl = l; }
        }
        lab[tid] = bestl;
    }
    __syncthreads();
    for (int s = tid; s < SLc; s += 256) {
        int n = s >> 2, k = s & 3;
        int base = n + 4 * k;
        int labs[4] = {lab[base], lab[base + 1], lab[base + 2], lab[base + 3]};
        int bestl = LQc, bestc = 0;
#pragma unroll
        for (int j = 0; j < 4; j++) {
            int c = 0;
#pragma unroll
            for (int j2 = 0; j2 < 4; j2++) c += (labs[j2] == labs[j]);
            if (c > bestc || (c == bestc && labs[j] < bestl)) { bestc = c; bestl = labs[j]; }
        }
        float* p = &Ab[bestl * Tc + base];
        atomicAdd(p + 0, 0.25f);
        atomicAdd(p + 1, 0.25f);
        atomicAdd(p + 2, 0.25f);
        atomicAdd(p + 3, 0.25f);
    }
    __syncthreads();
    for (int i = tid; i < LQc * Tc; i += 256) Amat[(long)b * LQc * Tc + i] = Ab[i];
    int warp = tid >> 5, lane = tid & 31;
    for (int l = warp; l < LQc; l += 8) {
        float s = 0.f;
        for (int t = lane; t < Tc; t += 32) s += Ab[l * Tc + t];
#pragma unroll
        for (int o = 16; o; o >>= 1) s += __shfl_down_sync(0xffffffff, s, o);
        if (lane == 0) cnt[b * LQc + l] = s;
    }
}

// ---------------- softmax weights (with inline su pooling) ----------------
__global__ void attnw_kernel(const float* __restrict__ sut, const float* __restrict__ bterm,
                             const float* __restrict__ cnt, const float* __restrict__ bP,
                             float* __restrict__ wcoef)
{
    const int bq = blockIdx.x;          // b*SL + q
    const int b = bq / SLc;
    const int q = bq % SLc;
    const int tid = threadIdx.x;        // 128: warp = head
    const int h = tid >> 5, l = tid & 31;
    const bool act = (l < LQc);
    const int j = l * Hc + h;

    float c_l = act ? cnt[b * LQc + l] : 0.f;
    float val;
    if (act) {
        int n = q >> 2, k = q & 3;
        int t0 = n + 4 * k;
        const float* p = sut + ((long)b * Tc + t0) * LHc + j;
        float su = (0.25f * (p[0] + p[LHc] + p[2 * LHc] + p[3 * LHc])
                    + bP[b * LHc + j]) * 0.0625f;
        val = su + bterm[b * LHc + j] * (1.f / 16.f);
    } else val = -INFINITY;
    float mval = (act && c_l > 0.f) ? val : -INFINITY;
#pragma unroll
    for (int o = 16; o; o >>= 1) mval = fmaxf(mval, __shfl_xor_sync(0xffffffff, mval, o));
    float e = act ? expf(val - mval) : 0.f;
    float zz = c_l * e;
#pragma unroll
    for (int o = 16; o; o >>= 1) zz += __shfl_xor_sync(0xffffffff, zz, o);
    if (act) wcoef[(long)bq * LHc + j] = (c_l > 0.f) ? (e / zz) : 0.f;
}

// ---------------- segment max pooling ----------------
__global__ void segmax_kernel(const float* __restrict__ outb, const int* __restrict__ vid_len,
                              float* __restrict__ mp)
{
    int idx = blockIdx.x * blockDim.x + threadIdx.x;
    if (idx >= Bc * Sc * Cc) return;
    int c = idx % Cc;
    int s = (idx / Cc) % Sc;
    int b = idx / (Sc * Cc);
    int Lb = vid_len[b] * Kc;
    int st = (s * Lb) / Sc;
    int en = ((s + 1) * Lb + Sc - 1) / Sc;
    float m = -INFINITY;
    const float* p = outb + ((long)b * SLc) * Cc + c;
    for (int t = st; t < en; t++) m = fmaxf(m, p[(long)t * Cc]);
    mp[idx] = m;
}

// ---------------- fused heads: pred (blocks 0..Bc*NW-1) + st/en (last 128) --------
__global__ void heads_kernel(const float* __restrict__ h, const float* __restrict__ w_p2,
                             const float* __restrict__ b_p2,
                             const float* __restrict__ mp,
                             const float* __restrict__ w_st, const float* __restrict__ b_st,
                             const float* __restrict__ w_en, const float* __restrict__ b_en,
                             float* __restrict__ out)
{
    const int tid = threadIdx.x, lane = tid & 31, warp = tid >> 5;
    if (blockIdx.x < Bc * NWc) {
        const int bn = blockIdx.x;
        const float* hr = h + (long)bn * Cc;
        __shared__ float r0[8], r1[8];
        float s0 = 0.f, s1 = 0.f;
        for (int i = tid; i < Cc; i += 256) {
            float hv = hr[i];
            s0 += hv * w_p2[i];
            s1 += hv * w_p2[Cc + i];
        }
#pragma unroll
        for (int o = 16; o; o >>= 1) {
            s0 += __shfl_down_sync(0xffffffff, s0, o);
            s1 += __shfl_down_sync(0xffffffff, s1, o);
        }
        if (lane == 0) { r0[warp] = s0; r1[warp] = s1; }
        __syncthreads();
        if (tid == 0) {
            float t0 = 0.f, t1 = 0.f;
#pragma unroll
            for (int w = 0; w < 8; w++) { t0 += r0[w]; t1 += r1[w]; }
            int b = bn / NWc, n = bn % NWc;
            out[(long)b * 2 * NWc + n] = t0 + b_p2[0];
            out[(long)b * 2 * NWc + NWc + n] = t1 + b_p2[1];
        }
    } else {
        const int id = blockIdx.x - Bc * NWc;  // 0..127
        const int b = id >> 4;
        const int r = id & 15;
        const int which = r >> 3;
        const int i = r & 7;
        const float* wgt = (which ? w_en : w_st) + (long)i * (Cc * Sc);
        __shared__ float red[8];
        float s = 0.f;
        for (int j = tid; j < Cc * Sc; j += 256) {
            int cc = j / Sc, ss = j % Sc;
            s += mp[((long)b * Sc + ss) * Cc + cc] * wgt[j];
        }
#pragma unroll
        for (int o = 16; o; o >>= 1) s += __shfl_down_sync(0xffffffff, s, o);
        if (lane == 0) red[warp] = s;
        __syncthreads();
        if (tid == 0) {
            float t = 0.f;
#pragma unroll
            for (int w = 0; w < 8; w++) t += red[w];
            float bias = (which ? b_en : b_st)[i];
            out[PRED_SZ + which * (Bc * Sc) + b * Sc + i] = t + bias;
        }
    }
}

// ---------------- host helpers ----------------
static inline dim3 tg(int M, int N, int batch) {
    return dim3((N + 63) / 64, (M + 63) / 64, batch);
}

static GDesc mk(const float* A, int lda, long sA1, long sA2,
                const float* B, int ldb, long sB1, long sB2,
                float* C, int ldc, long sC1, long sC2,
                int M, int N, int K, int bdiv, const float* bias, float alpha,
                int transB, int relu, int batch, int& cursor)
{
    GDesc d;
    d.A = A; d.B = B; d.C = C; d.bias = bias;
    d.lda = lda; d.ldb = ldb; d.ldc = ldc;
    d.sA1 = sA1; d.sA2 = sA2; d.sB1 = sB1; d.sB2 = sB2; d.sC1 = sC1; d.sC2 = sC2;
    d.M = M; d.N = N; d.K = K; d.bdiv = bdiv;
    d.transB = transB; d.relu = relu; d.alpha = alpha;
    d.tilesX = (N + 63) / 64;
    int tilesY = (M + 63) / 64;
    d.tilesPerBatch = d.tilesX * tilesY;
    d.tileStart = cursor;
    cursor += d.tilesPerBatch * batch;
    return d;
}

extern "C" void kernel_launch(void* const* d_in, const int* in_sizes, int n_in,
                              void* d_out, int out_size)
{
    const float* vis   = (const float*)d_in[0];
    const float* query = (const float*)d_in[1];
    const int*   vlen  = (const int*)  d_in[2];
    const float* w_v1  = (const float*)d_in[3];
    const float* b_v1  = (const float*)d_in[4];
    const float* w_v2  = (const float*)d_in[5];
    const float* b_v2  = (const float*)d_in[6];
    const float* w_s1  = (const float*)d_in[7];
    const float* b_s1  = (const float*)d_in[8];
    const float* w_s2  = (const float*)d_in[9];
    const float* b_s2  = (const float*)d_in[10];
    const float* w_in  = (const float*)d_in[11];
    const float* b_in  = (const float*)d_in[12];
    const float* w_out = (const float*)d_in[13];
    const float* b_out = (const float*)d_in[14];
    const float* w_p1  = (const float*)d_in[15];
    const float* b_p1  = (const float*)d_in[16];
    const float* w_p2  = (const float*)d_in[17];
    const float* b_p2  = (const float*)d_in[18];
    const float* w_st  = (const float*)d_in[19];
    const float* b_st  = (const float*)d_in[20];
    const float* w_en  = (const float*)d_in[21];
    const float* b_en  = (const float*)d_in[22];
    float* out = (float*)d_out;

    float *xpe, *qpe, *Wc, *qbias, *qbv, *e1, *e2, *e2k, *F, *sim, *biasl,
          *cnt, *P, *W2P, *bterm, *bP, *sut, *wcoef, *Amat, *tmp,
          *qsum, *VS, *VSo, *outb, *G, *bconst, *hbuf, *mp;
    cudaGetSymbolAddress((void**)&xpe,   g_xpe);
    cudaGetSymbolAddress((void**)&qpe,   g_qpe);
    cudaGetSymbolAddress((void**)&Wc,    g_Wc);
    cudaGetSymbolAddress((void**)&qbias, g_qbias);
    cudaGetSymbolAddress((void**)&qbv,   g_qbv);
    cudaGetSymbolAddress((void**)&e1,    g_e1);
    cudaGetSymbolAddress((void**)&e2,    g_e2);
    cudaGetSymbolAddress((void**)&e2k,   g_e2k);
    cudaGetSymbolAddress((void**)&F,     g_F);
    cudaGetSymbolAddress((void**)&sim,   g_sim);
    cudaGetSymbolAddress((void**)&biasl, g_biasl);
    cudaGetSymbolAddress((void**)&cnt,   g_cnt);
    cudaGetSymbolAddress((void**)&P,     g_P);
    cudaGetSymbolAddress((void**)&W2P,   g_W2P);
    cudaGetSymbolAddress((void**)&bterm, g_bterm);
    cudaGetSymbolAddress((void**)&bP,    g_bP);
    cudaGetSymbolAddress((void**)&sut,   g_sut);
    cudaGetSymbolAddress((void**)&wcoef, g_wcoef);
    cudaGetSymbolAddress((void**)&Amat,  g_Amat);
    cudaGetSymbolAddress((void**)&tmp,   g_tmp);
    cudaGetSymbolAddress((void**)&qsum,  g_qsum);
    cudaGetSymbolAddress((void**)&VS,    g_VS);
    cudaGetSymbolAddress((void**)&VSo,   g_VSo);
    cudaGetSymbolAddress((void**)&outb,  g_outb);
    cudaGetSymbolAddress((void**)&G,     g_G);
    cudaGetSymbolAddress((void**)&bconst,g_bconst);
    cudaGetSymbolAddress((void**)&hbuf,  g_hbuf);
    cudaGetSymbolAddress((void**)&mp,    g_mp);

    // 1. fused positional encodings
    {
        int n = Bc * Tc * Cc + Bc * LQc * QDc;
        pe2_kernel<<<(n + 255) / 256, 256>>>(vis, query, xpe, qpe);
    }
    // 2. fused qbias + bconst; then qbv
    qb2_kernel<<<(2 * Cc * 32 + 255) / 256, 256>>>(w_v2, b_v1, b_v2,
                                                   w_p1, b_out, b_p1, qbias, bconst);
    qbv_kernel<<<(Cc * 32 + 255) / 256, 256>>>(qbias, w_in + 2L * Cc * Cc, b_in + 2 * Cc, qbv);

    // 3. G1: [Wc, e1, e2]
    {
        int cur = 0;
        GPack pk; pk.n = 3;
        pk.g[0] = mk(w_v2, Cc, 0, 0, w_v1, Cc, 0, 0, Wc, Cc, 0, 0,
                     Cc, Cc, Cc, 1, nullptr, 1.f, 0, 0, 1, cur);
        pk.g[1] = mk(qpe, QDc, 0, 0, w_s1, QDc, 0, 0, e1, Cc, 0, 0,
                     Bc * LQc, Cc, QDc, 1, b_s1, 1.f, 1, 0, 1, cur);
        pk.g[2] = mk(qpe, QDc, 0, 0, w_s2, QDc, 0, 0, e2, Cc, 0, 0,
                     Bc * LQc, Cc, QDc, 1, b_s2, 1.f, 1, 0, 1, cur);
        ggemm_kernel<<<cur, 128>>>(pk);
    }

    // 4. G2: [F = e1 @ w_v1 (NN), e2k = e2 @ wk^T + bk (TB)]
    {
        int cur = 0;
        GPack pk; pk.n = 2;
        pk.g[0] = mk(e1, Cc, 0, 0, w_v1, Cc, 0, 0, F, Cc, 0, 0,
                     Bc * LQc, Cc, Cc, 1, nullptr, 1.f, 0, 0, 1, cur);
        pk.g[1] = mk(e2, Cc, 0, 0, w_in + (long)Cc * Cc, Cc, 0, 0, e2k, Cc, 0, 0,
                     Bc * LQc, Cc, Cc, 1, b_in + Cc, 1.f, 1, 0, 1, cur);
        ggemm_kernel<<<cur, 128>>>(pk);
    }

    // 5. G3: [sim = xpe @ F^T (TB, batch 8), P = e2k_h @ wq_h (NN, batch 4)]
    {
        int cur = 0;
        GPack pk; pk.n = 2;
        pk.g[0] = mk(xpe, Cc, (long)Tc * Cc, 0, F, Cc, (long)LQc * Cc, 0,
                     sim, LQc, (long)Tc * LQc, 0,
                     Tc, LQc, Cc, 1, nullptr, 1.f, 1, 0, Bc, cur);
        pk.g[1] = mk(e2k, Cc, (long)HDc, 0, w_in, Cc, (long)HDc * Cc, 0,
                     P, Hc * Cc, (long)Cc, 0,
                     Bc * LQc, Cc, HDc, 1, nullptr, 1.f, 0, 0, Hc, cur);
        ggemm_kernel<<<cur, 128>>>(pk);
    }

    // 6. fused dots (biasl, bterm, bP)
    {
        int warps = Bc * LQc + 2 * Bc * LHc;   // 1728
        dots_kernel<<<(warps * 32 + 255) / 256, 256>>>(e1, b_v1, e2k, b_in, P, qbias,
                                                       biasl, bterm, bP);
    }

    // 7. fused argmax + mode + Amat + cnt
    amatcnt_kernel<<<Bc, 256>>>(sim, biasl, Amat, cnt);

    // 8. G4: [W2P = P @ Wc (NN, batch 8), tmp = Amat @ xpe (NN, batch 8)]
    {
        int cur = 0;
        GPack pk; pk.n = 2;
        pk.g[0] = mk(P, Cc, (long)LHc * Cc, 0, Wc, Cc, 0, 0,
                     W2P, Cc, (long)LHc * Cc, 0,
                     LHc, Cc, Cc, 1, nullptr, 1.f, 0, 0, Bc, cur);
        pk.g[1] = mk(Amat, Tc, (long)LQc * Tc, 0, xpe, Cc, (long)Tc * Cc, 0,
                     tmp, Cc, (long)LQc * Cc, 0,
                     LQc, Cc, Tc, 1, nullptr, 1.f, 0, 0, Bc, cur);
        ggemm_kernel<<<cur, 128>>>(pk);
    }

    // 9. G5: [sut = xpe @ W2P^T (TB, batch 8), qsum = tmp @ Wc^T (TB)]
    {
        int cur = 0;
        GPack pk; pk.n = 2;
        pk.g[0] = mk(xpe, Cc, (long)Tc * Cc, 0, W2P, Cc, (long)LHc * Cc, 0,
                     sut, LHc, (long)Tc * LHc, 0,
                     Tc, LHc, Cc, 1, nullptr, 1.f, 1, 0, Bc, cur);
        pk.g[1] = mk(tmp, Cc, 0, 0, Wc, Cc, 0, 0, qsum, Cc, 0, 0,
                     Bc * LQc, Cc, Cc, 1, nullptr, 1.f, 1, 0, 1, cur);
        ggemm_kernel<<<cur, 128>>>(pk);
    }

    // 10. attnw (inline pooling) -> wcoef
    attnw_kernel<<<Bc * SLc, 128>>>(sut, bterm, cnt, bP, wcoef);

    // 11. VS = qsum @ wv^T + cnt[row]*qbv[col] (fused epilogue) ; VSo (TB batch 4)
    gemm_kernel<true, false><<<tg(Bc * LQc, Cc, 1), 128>>>(
        qsum, Cc, 0, 0, w_in + 2L * Cc * Cc, Cc, 0, 0, VS, Cc, 0, 0,
        Bc * LQc, Cc, Cc, 1, nullptr, 1.f, cnt, qbv);
    gemm_kernel<true, false><<<tg(Bc * LQc, Cc, Hc), 128>>>(
        VS, Cc, (long)HDc, 0,
        w_out, Cc, (long)HDc, 0,
        VSo, Hc * Cc, (long)Cc, 0,
        Bc * LQc, Cc, HDc, 1, nullptr, 1.f, nullptr, nullptr);

    // 12. G6: [G = VSo @ w_p1_j^T (TB, batch 32), outb = wcoef @ VSo (NN, batch 8)]
    {
        int cur = 0;
        GPack pk; pk.n = 2;
        pk.g[0] = mk(VSo, Cc, (long)LHc * Cc, 0,
                     w_p1, Kc * Cc, 0, (long)Cc,
                     G, Cc, (long)Kc * LHc * Cc, (long)LHc * Cc,
                     LHc, Cc, Cc, Kc, nullptr, 1.f, 1, 0, Bc * Kc, cur);
        pk.g[1] = mk(wcoef, LHc, (long)SLc * LHc, 0,
                     VSo, Cc, (long)LHc * Cc, 0,
                     outb, Cc, (long)SLc * Cc, 0,
                     SLc, Cc, LHc, 1, b_out, 1.f, 0, 0, Bc, cur);
        ggemm_kernel<<<cur, 128>>>(pk);
    }

    // 13. segmax (needs outb only) ; hbuf (needs G + wcoef)
    segmax_kernel<<<(Bc * Sc * Cc + 255) / 256, 256>>>(outb, vlen, mp);
    gemm_kernel<false, true><<<tg(NWc, Cc, Bc), 128>>>(
        wcoef, Kc * LHc, (long)SLc * LHc, 0,
        G, Cc, (long)Kc * LHc * Cc, 0,
        hbuf, Cc, (long)NWc * Cc, 0,
        NWc, Cc, Kc * LHc, 1, bconst, 1.f, nullptr, nullptr);

    // 14. fused heads (pred + st/en)
    heads_kernel<<<Bc * NWc + 128, 256>>>(hbuf, w_p2, b_p2, mp,
                                          w_st, b_st, w_en, b_en, out);
}

// round 17
// speedup vs baseline: 1.1807x; 1.0482x over previous
#include <cuda_runtime.h>
#include <cstdint>
#include <math.h>

// ---------------- problem constants ----------------
constexpr int Bc  = 8;
constexpr int Tc  = 256;
constexpr int Cc  = 1024;
constexpr int QDc = 768;
constexpr int LQc = 24;
constexpr int Kc  = 4;
constexpr int NWc = 241;     // T - W + 1
constexpr int Sc  = 8;
constexpr int Hc  = 4;
constexpr int HDc = 256;     // C/H
constexpr int SLc = 964;     // NW*K
constexpr int LHc = LQc * Hc; // 96

constexpr int PRED_SZ = Bc * 2 * NWc;  // 3856

// ---------------- scratch (device globals; no allocation allowed) ----------------
__device__ __align__(16) float g_xpe   [Bc * Tc * Cc];
__device__ __align__(16) float g_qpe   [Bc * LQc * QDc];
__device__ __align__(16) float g_Wc    [Cc * Cc];
__device__ __align__(16) float g_qbias [Cc];
__device__ __align__(16) float g_qbv   [Cc];
__device__ __align__(16) float g_e1    [Bc * LQc * Cc];
__device__ __align__(16) float g_e2    [Bc * LQc * Cc];
__device__ __align__(16) float g_e2k   [Bc * LQc * Cc];
__device__ __align__(16) float g_F     [Bc * LQc * Cc];
__device__ __align__(16) float g_sim   [Bc * Tc * LQc];
__device__ __align__(16) float g_biasl [Bc * LQc];
__device__ __align__(16) int   g_labels[Bc * Tc];
__device__ __align__(16) float g_cnt   [Bc * LQc];
__device__ __align__(16) float g_P     [Bc * LHc * Cc];
__device__ __align__(16) float g_W2P   [Bc * LHc * Cc];
__device__ __align__(16) float g_bterm [Bc * LHc];
__device__ __align__(16) float g_bP    [Bc * LHc];
__device__ __align__(16) float g_sut   [Bc * Tc * LHc];
__device__ __align__(16) float g_wcoef [Bc * SLc * LHc];
__device__ __align__(16) float g_Amat  [Bc * LQc * Tc];
__device__ __align__(16) float g_tmp   [Bc * LQc * Cc];
__device__ __align__(16) float g_qsum  [Bc * LQc * Cc];
__device__ __align__(16) float g_VS    [Bc * LQc * Cc];
__device__ __align__(16) float g_VSo   [Bc * LHc * Cc];
__device__ __align__(16) float g_outb  [Bc * SLc * Cc];
__device__ __align__(16) float g_G     [Bc * Kc * LHc * Cc];
__device__ __align__(16) float g_bconst[Cc];
__device__ __align__(16) float g_hbuf  [Bc * NWc * Cc];
__device__ __align__(16) float g_mp    [Bc * Sc * Cc];

// ---------------- grouped GEMM descriptor ----------------
struct GDesc {
    const float* A; const float* B; float* C; const float* bias;
    int lda, ldb, ldc;
    long sA1, sA2, sB1, sB2, sC1, sC2;
    int M, N, K, bdiv;
    int transB, relu;
    float alpha;
    int tileStart, tilesPerBatch, tilesX;
    int mblk;           // if >0: C row gm -> (gm/mblk)*sMblk + (gm%mblk)*ldc
    long sMblk;
};
struct GPack { GDesc g[3]; int n; };

// ---------------- grouped GEMM: 64x64 tile, 128 threads, 8x4 microtile ----------------
__global__ void __launch_bounds__(128) ggemm_kernel(GPack pk)
{
    __shared__ float As[2][16][68];
    __shared__ float Bs[2][16][68];

    int id = blockIdx.x;
    int gi = 0;
    if (pk.n > 1 && id >= pk.g[1].tileStart) gi = 1;
    if (pk.n > 2 && id >= pk.g[2].tileStart) gi = 2;
    const GDesc& d = pk.g[gi];
    int local = id - d.tileStart;
    int z  = local / d.tilesPerBatch;
    int t  = local - z * d.tilesPerBatch;
    int by = t / d.tilesX;
    int bx = t - by * d.tilesX;
    int z1 = z / d.bdiv, z2 = z - z1 * d.bdiv;

    const float* A = d.A + z1 * d.sA1 + z2 * d.sA2;
    const float* B = d.B + z1 * d.sB1 + z2 * d.sB2;
    float*       C = d.C + z1 * d.sC1 + z2 * d.sC2;
    const int M = d.M, N = d.N, K = d.K;
    const int lda = d.lda, ldb = d.ldb, ldc = d.ldc;
    const bool TRANSB = d.transB;

    const int tid = threadIdx.x;        // 128 threads
    const int tx = tid & 15;
    const int trow = tid >> 4;
    const int rowBase = by * 64;
    const int colBase = bx * 64;

    float acc[8][4] = {};
    float sa[8];
    float sb[8];

    auto loadTiles = [&](int k0) {
#pragma unroll
        for (int i = 0; i < 8; i++) {
            int l = tid + i * 128;
            int m = l >> 4, kk = l & 15;
            int gm = rowBase + m;
            sa[i] = (gm < M) ? A[(long)gm * lda + k0 + kk] : 0.f;
        }
        if (TRANSB) {
            int n = tid >> 1, k8 = (tid & 1) * 8;
            int gn = colBase + n;
            if (gn < N) {
                float4 v0 = *(const float4*)(B + (long)gn * ldb + k0 + k8);
                float4 v1 = *(const float4*)(B + (long)gn * ldb + k0 + k8 + 4);
                sb[0] = v0.x; sb[1] = v0.y; sb[2] = v0.z; sb[3] = v0.w;
                sb[4] = v1.x; sb[5] = v1.y; sb[6] = v1.z; sb[7] = v1.w;
            } else {
#pragma unroll
                for (int j = 0; j < 8; j++) sb[j] = 0.f;
            }
        } else {
#pragma unroll
            for (int i = 0; i < 8; i++) {
                int l = tid + i * 128;
                int kk = l >> 6, n = l & 63;
                int gn = colBase + n;
                sb[i] = (gn < N) ? B[(long)(k0 + kk) * ldb + gn] : 0.f;
            }
        }
    };
    auto storeTiles = [&](int p) {
#pragma unroll
        for (int i = 0; i < 8; i++) {
            int l = tid + i * 128;
            int m = l >> 4, kk = l & 15;
            As[p][kk][m] = sa[i];
        }
        if (TRANSB) {
            int n = tid >> 1, k8 = (tid & 1) * 8;
#pragma unroll
            for (int j = 0; j < 8; j++) Bs[p][k8 + j][n] = sb[j];
        } else {
#pragma unroll
            for (int i = 0; i < 8; i++) {
                int l = tid + i * 128;
                int kk = l >> 6, n = l & 63;
                Bs[p][kk][n] = sb[i];
            }
        }
    };

    loadTiles(0);
    storeTiles(0);
    __syncthreads();

    int p = 0;
    for (int k0 = 0; k0 < K; k0 += 16) {
        const bool hasNext = (k0 + 16 < K);
        if (hasNext) loadTiles(k0 + 16);

#pragma unroll
        for (int kk = 0; kk < 16; kk++) {
            const float* arow = &As[p][kk][trow * 8];
            float4 a0 = *(const float4*)arow;
            float4 a1 = *(const float4*)(arow + 4);
            float4 b0 = *(const float4*)&Bs[p][kk][tx * 4];
            float ra[8] = {a0.x, a0.y, a0.z, a0.w, a1.x, a1.y, a1.z, a1.w};
            float rb[4] = {b0.x, b0.y, b0.z, b0.w};
#pragma unroll
            for (int i = 0; i < 8; i++)
#pragma unroll
                for (int j = 0; j < 4; j++)
                    acc[i][j] += ra[i] * rb[j];
        }
        if (hasNext) storeTiles(1 - p);
        __syncthreads();
        p ^= 1;
    }

#pragma unroll
    for (int i = 0; i < 8; i++) {
        int gm = rowBase + trow * 8 + i;
        if (gm >= M) continue;
        long rowOff;
        if (d.mblk > 0) rowOff = (long)(gm / d.mblk) * d.sMblk + (long)(gm % d.mblk) * ldc;
        else            rowOff = (long)gm * ldc;
        int gn0 = colBase + tx * 4;
#pragma unroll
        for (int j = 0; j < 4; j++) {
            int gn = gn0 + j;
            if (gn >= N) continue;
            float val = acc[i][j] * d.alpha + (d.bias ? d.bias[gn] : 0.f);
            if (d.relu) val = fmaxf(val, 0.f);
            C[rowOff + gn] = val;
        }
    }
}

// ---------------- singleton tiled GEMM: 64x64 tile, 128 threads, 8x4 microtile ------
template<bool TRANSB, bool RELU>
__global__ void __launch_bounds__(128) gemm_kernel(
    const float* __restrict__ A, int lda, long sA1, long sA2,
    const float* __restrict__ B, int ldb, long sB1, long sB2,
    float* __restrict__ Cm, int ldc, long sC1, long sC2,
    int M, int N, int K, int bdiv,
    const float* __restrict__ bias, float alpha)
{
    __shared__ float As[2][16][68];
    __shared__ float Bs[2][16][68];

    const int z = blockIdx.z, z1 = z / bdiv, z2 = z % bdiv;
    A  += z1 * sA1 + z2 * sA2;
    B  += z1 * sB1 + z2 * sB2;
    Cm += z1 * sC1 + z2 * sC2;

    const int tid = threadIdx.x;        // 128 threads
    const int tx = tid & 15;
    const int trow = tid >> 4;
    const int rowBase = blockIdx.y * 64;
    const int colBase = blockIdx.x * 64;

    float acc[8][4] = {};
    float sa[8];
    float sb[8];

    auto loadTiles = [&](int k0) {
#pragma unroll
        for (int i = 0; i < 8; i++) {
            int l = tid + i * 128;
            int m = l >> 4, kk = l & 15;
            int gm = rowBase + m;
            sa[i] = (gm < M) ? A[(long)gm * lda + k0 + kk] : 0.f;
        }
        if (TRANSB) {
            int n = tid >> 1, k8 = (tid & 1) * 8;
            int gn = colBase + n;
            if (gn < N) {
                float4 v0 = *(const float4*)(B + (long)gn * ldb + k0 + k8);
                float4 v1 = *(const float4*)(B + (long)gn * ldb + k0 + k8 + 4);
                sb[0] = v0.x; sb[1] = v0.y; sb[2] = v0.z; sb[3] = v0.w;
                sb[4] = v1.x; sb[5] = v1.y; sb[6] = v1.z; sb[7] = v1.w;
            } else {
#pragma unroll
                for (int j = 0; j < 8; j++) sb[j] = 0.f;
            }
        } else {
#pragma unroll
            for (int i = 0; i < 8; i++) {
                int l = tid + i * 128;
                int kk = l >> 6, n = l & 63;
                int gn = colBase + n;
                sb[i] = (gn < N) ? B[(long)(k0 + kk) * ldb + gn] : 0.f;
            }
        }
    };
    auto storeTiles = [&](int p) {
#pragma unroll
        for (int i = 0; i < 8; i++) {
            int l = tid + i * 128;
            int m = l >> 4, kk = l & 15;
            As[p][kk][m] = sa[i];
        }
        if (TRANSB) {
            int n = tid >> 1, k8 = (tid & 1) * 8;
#pragma unroll
            for (int j = 0; j < 8; j++) Bs[p][k8 + j][n] = sb[j];
        } else {
#pragma unroll
            for (int i = 0; i < 8; i++) {
                int l = tid + i * 128;
                int kk = l >> 6, n = l & 63;
                Bs[p][kk][n] = sb[i];
            }
        }
    };

    loadTiles(0);
    storeTiles(0);
    __syncthreads();

    int p = 0;
    for (int k0 = 0; k0 < K; k0 += 16) {
        const bool hasNext = (k0 + 16 < K);
        if (hasNext) loadTiles(k0 + 16);

#pragma unroll
        for (int kk = 0; kk < 16; kk++) {
            const float* arow = &As[p][kk][trow * 8];
            float4 a0 = *(const float4*)arow;
            float4 a1 = *(const float4*)(arow + 4);
            float4 b0 = *(const float4*)&Bs[p][kk][tx * 4];
            float ra[8] = {a0.x, a0.y, a0.z, a0.w, a1.x, a1.y, a1.z, a1.w};
            float rb[4] = {b0.x, b0.y, b0.z, b0.w};
#pragma unroll
            for (int i = 0; i < 8; i++)
#pragma unroll
                for (int j = 0; j < 4; j++)
                    acc[i][j] += ra[i] * rb[j];
        }
        if (hasNext) storeTiles(1 - p);
        __syncthreads();
        p ^= 1;
    }

#pragma unroll
    for (int i = 0; i < 8; i++) {
        int gm = rowBase + trow * 8 + i;
        if (gm >= M) continue;
        int gn0 = colBase + tx * 4;
#pragma unroll
        for (int j = 0; j < 4; j++) {
            int gn = gn0 + j;
            if (gn >= N) continue;
            float val = acc[i][j] * alpha + (bias ? bias[gn] : 0.f);
            if (RELU) val = fmaxf(val, 0.f);
            Cm[(long)gm * ldc + gn] = val;
        }
    }
}

// ---------------- fused positional encodings (vis + query) ----------------
__global__ void pe2_kernel(const float* __restrict__ vis, const float* __restrict__ query,
                           float* __restrict__ xpe, float* __restrict__ qpe)
{
    const int n1 = Bc * Tc * Cc;
    const int n2 = Bc * LQc * QDc;
    int idx = blockIdx.x * blockDim.x + threadIdx.x;
    const float* src; float* dst; int local, L, D;
    if (idx < n1) { src = vis; dst = xpe; local = idx; L = Tc; D = Cc; }
    else if (idx < n1 + n2) { src = query; dst = qpe; local = idx - n1; L = LQc; D = QDc; }
    else return;
    int c = local % D;
    int pos = (local / D) % L;
    int i2 = (c >> 1) * 2;
    float freq = expf((float)i2 * (-logf(10000.f) / (float)D));
    float ang = (float)pos * freq;
    float pe = (c & 1) ? cosf(ang) : sinf(ang);
    dst[local] = src[local] + pe;
}

// ---------------- fused qbias + bconst (independent warp-dots) ----------------
__global__ void qb2_kernel(const float* __restrict__ w_v2, const float* __restrict__ b_v1,
                           const float* __restrict__ b_v2,
                           const float* __restrict__ w_p1, const float* __restrict__ b_out,
                           const float* __restrict__ b_p1,
                           float* __restrict__ qbias, float* __restrict__ bconst)
{
    int gw = (blockIdx.x * blockDim.x + threadIdx.x) >> 5;
    int lane = threadIdx.x & 31;
    if (gw < Cc) {
        const float* row = w_v2 + (long)gw * Cc;
        float s = 0.f;
        for (int i = lane; i < Cc; i += 32) s += row[i] * b_v1[i];
#pragma unroll
        for (int o = 16; o; o >>= 1) s += __shfl_down_sync(0xffffffff, s, o);
        if (lane == 0) qbias[gw] = s + b_v2[gw];
    } else if (gw < 2 * Cc) {
        int w = gw - Cc;
        const float* row = w_p1 + (long)w * (Kc * Cc);
        float s = 0.f;
        for (int i = lane; i < Kc * Cc; i += 32) s += row[i] * b_out[i & (Cc - 1)];
#pragma unroll
        for (int o = 16; o; o >>= 1) s += __shfl_down_sync(0xffffffff, s, o);
        if (lane == 0) bconst[w] = s + b_p1[w];
    }
}

// ---------------- qbv[c] = qbias . wv[c,:] + bv[c] ----------------
__global__ void qbv_kernel(const float* __restrict__ qbias, const float* __restrict__ wv,
                           const float* __restrict__ bv, float* __restrict__ qbv)
{
    int w = (blockIdx.x * blockDim.x + threadIdx.x) >> 5;
    int lane = threadIdx.x & 31;
    if (w >= Cc) return;
    const float* row = wv + (long)w * Cc;
    float s = 0.f;
    for (int i = lane; i < Cc; i += 32) s += row[i] * qbias[i];
#pragma unroll
    for (int o = 16; o; o >>= 1) s += __shfl_down_sync(0xffffffff, s, o);
    if (lane == 0) qbv[w] = s + bv[w];
}

// ---------------- fused warp-dots: biasl, bterm, bP ----------------
__global__ void dots_kernel(const float* __restrict__ e1, const float* __restrict__ b_v1,
                            const float* __restrict__ e2k, const float* __restrict__ b_in,
                            const float* __restrict__ P, const float* __restrict__ qbias,
                            float* __restrict__ biasl, float* __restrict__ bterm,
                            float* __restrict__ bP)
{
    int gw = (blockIdx.x * blockDim.x + threadIdx.x) >> 5;
    int lane = threadIdx.x & 31;
    if (gw < Bc * LQc) {
        const float* row = e1 + (long)gw * Cc;
        float s = 0.f;
        for (int i = lane; i < Cc; i += 32) s += row[i] * b_v1[i];
#pragma unroll
        for (int o = 16; o; o >>= 1) s += __shfl_down_sync(0xffffffff, s, o);
        if (lane == 0) biasl[gw] = s;
    } else if (gw < Bc * LQc + Bc * LHc) {
        int idx = gw - Bc * LQc;
        int b = idx / LHc, j = idx % LHc;
        int l = j / Hc, h = j % Hc;
        const float* e = e2k + ((long)b * LQc + l) * Cc + h * HDc;
        const float* bq = b_in + h * HDc;
        float s = 0.f;
        for (int i = lane; i < HDc; i += 32) s += bq[i] * e[i];
#pragma unroll
        for (int o = 16; o; o >>= 1) s += __shfl_down_sync(0xffffffff, s, o);
        if (lane == 0) bterm[idx] = s;
    } else if (gw < Bc * LQc + 2 * Bc * LHc) {
        int idx = gw - Bc * LQc - Bc * LHc;
        const float* row = P + (long)idx * Cc;
        float s = 0.f;
        for (int i = lane; i < Cc; i += 32) s += row[i] * qbias[i];
#pragma unroll
        for (int o = 16; o; o >>= 1) s += __shfl_down_sync(0xffffffff, s, o);
        if (lane == 0) bP[idx] = s;
    }
}

// ---------------- labels = argmax_l (sim + biasl) ----------------
__global__ void argmax_kernel(const float* __restrict__ sim, const float* __restrict__ biasl,
                              int* __restrict__ labels)
{
    int idx = blockIdx.x * blockDim.x + threadIdx.x;
    if (idx >= Bc * Tc) return;
    int b = idx / Tc;
    const float* p = sim + (long)idx * LQc;
    const float* bl = biasl + b * LQc;
    float best = -INFINITY; int bestl = 0;
#pragma unroll
    for (int l = 0; l < LQc; l++) {
        float v = p[l] + bl[l];
        if (v > best) { best = v; bestl = l; }
    }
    labels[idx] = bestl;
}

// ---------------- fused mode + Amat + cnt (per-batch block) ----------------
__global__ void amatcnt_kernel(const int* __restrict__ labels,
                               float* __restrict__ Amat, float* __restrict__ cnt)
{
    const int b = blockIdx.x;
    const int tid = threadIdx.x;      // 256
    __shared__ float Ab[LQc * Tc];
    __shared__ int lab[Tc];
    for (int i = tid; i < LQc * Tc; i += 256) Ab[i] = 0.f;
    if (tid < Tc) lab[tid] = labels[b * Tc + tid];
    __syncthreads();
    for (int s = tid; s < SLc; s += 256) {
        int n = s >> 2, k = s & 3;
        int base = n + 4 * k;
        int labs[4] = {lab[base], lab[base + 1], lab[base + 2], lab[base + 3]};
        int bestl = LQc, bestc = 0;
#pragma unroll
        for (int j = 0; j < 4; j++) {
            int c = 0;
#pragma unroll
            for (int j2 = 0; j2 < 4; j2++) c += (labs[j2] == labs[j]);
            if (c > bestc || (c == bestc && labs[j] < bestl)) { bestc = c; bestl = labs[j]; }
        }
        float* p = &Ab[bestl * Tc + base];
        atomicAdd(p + 0, 0.25f);
        atomicAdd(p + 1, 0.25f);
        atomicAdd(p + 2, 0.25f);
        atomicAdd(p + 3, 0.25f);
    }
    __syncthreads();
    for (int i = tid; i < LQc * Tc; i += 256) Amat[(long)b * LQc * Tc + i] = Ab[i];
    int warp = tid >> 5, lane = tid & 31;
    for (int l = warp; l < LQc; l += 8) {
        float s = 0.f;
        for (int t = lane; t < Tc; t += 32) s += Ab[l * Tc + t];
#pragma unroll
        for (int o = 16; o; o >>= 1) s += __shfl_down_sync(0xffffffff, s, o);
        if (lane == 0) cnt[b * LQc + l] = s;
    }
}

// ---------------- softmax weights (with inline su pooling) ----------------
__global__ void attnw_kernel(const float* __restrict__ sut, const float* __restrict__ bterm,
                             const float* __restrict__ cnt, const float* __restrict__ bP,
                             float* __restrict__ wcoef)
{
    const int bq = blockIdx.x;          // b*SL + q
    const int b = bq / SLc;
    const int q = bq % SLc;
    const int tid = threadIdx.x;        // 128: warp = head
    const int h = tid >> 5, l = tid & 31;
    const bool act = (l < LQc);
    const int j = l * Hc + h;

    float c_l = act ? cnt[b * LQc + l] : 0.f;
    float val;
    if (act) {
        int n = q >> 2, k = q & 3;
        int t0 = n + 4 * k;
        const float* p = sut + ((long)b * Tc + t0) * LHc + j;
        float su = (0.25f * (p[0] + p[LHc] + p[2 * LHc] + p[3 * LHc])
                    + bP[b * LHc + j]) * 0.0625f;
        val = su + bterm[b * LHc + j] * (1.f / 16.f);
    } else val = -INFINITY;
    float mval = (act && c_l > 0.f) ? val : -INFINITY;
#pragma unroll
    for (int o = 16; o; o >>= 1) mval = fmaxf(mval, __shfl_xor_sync(0xffffffff, mval, o));
    float e = act ? expf(val - mval) : 0.f;
    float zz = c_l * e;
#pragma unroll
    for (int o = 16; o; o >>= 1) zz += __shfl_xor_sync(0xffffffff, zz, o);
    if (act) wcoef[(long)bq * LHc + j] = (c_l > 0.f) ? (e / zz) : 0.f;
}

// ---------------- VS += cnt * qbv ----------------
__global__ void vsfix_kernel(float* __restrict__ VS, const float* __restrict__ cnt,
                             const float* __restrict__ qbv)
{
    int idx = blockIdx.x * blockDim.x + threadIdx.x;
    if (idx >= Bc * LQc * Cc) return;
    int c = idx % Cc;
    int bl = idx / Cc;
    VS[idx] += cnt[bl] * qbv[c];
}

// ---------------- pred head ----------------
__global__ void pred_kernel(const float* __restrict__ h, const float* __restrict__ w_p2,
                            const float* __restrict__ b_p2, float* __restrict__ out)
{
    const int bn = blockIdx.x;           // b*NW + n
    const float* hr = h + (long)bn * Cc;
    __shared__ float r0[8], r1[8];
    const int tid = threadIdx.x, lane = tid & 31, warp = tid >> 5;
    float s0 = 0.f, s1 = 0.f;
    for (int i = tid; i < Cc; i += 256) {
        float hv = hr[i];
        s0 += hv * w_p2[i];
        s1 += hv * w_p2[Cc + i];
    }
#pragma unroll
    for (int o = 16; o; o >>= 1) {
        s0 += __shfl_down_sync(0xffffffff, s0, o);
        s1 += __shfl_down_sync(0xffffffff, s1, o);
    }
    if (lane == 0) { r0[warp] = s0; r1[warp] = s1; }
    __syncthreads();
    if (tid == 0) {
        float t0 = 0.f, t1 = 0.f;
#pragma unroll
        for (int w = 0; w < 8; w++) { t0 += r0[w]; t1 += r1[w]; }
        int b = bn / NWc, n = bn % NWc;
        out[(long)b * 2 * NWc + n] = t0 + b_p2[0];
        out[(long)b * 2 * NWc + NWc + n] = t1 + b_p2[1];
    }
}

// ---------------- segment max pooling ----------------
__global__ void segmax_kernel(const float* __restrict__ outb, const int* __restrict__ vid_len,
                              float* __restrict__ mp)
{
    int idx = blockIdx.x * blockDim.x + threadIdx.x;
    if (idx >= Bc * Sc * Cc) return;
    int c = idx % Cc;
    int s = (idx / Cc) % Sc;
    int b = idx / (Sc * Cc);
    int Lb = vid_len[b] * Kc;
    int st = (s * Lb) / Sc;
    int en = ((s + 1) * Lb + Sc - 1) / Sc;
    float m = -INFINITY;
    const float* p = outb + ((long)b * SLc) * Cc + c;
    for (int t = st; t < en; t++) m = fmaxf(m, p[(long)t * Cc]);
    mp[idx] = m;
}

// ---------------- st/en heads ----------------
__global__ void sten_kernel(const float* __restrict__ mp,
                            const float* __restrict__ w_st, const float* __restrict__ b_st,
                            const float* __restrict__ w_en, const float* __restrict__ b_en,
                            float* __restrict__ out)
{
    const int id = blockIdx.x;           // 0..127
    const int b = id >> 4;
    const int r = id & 15;
    const int which = r >> 3;
    const int i = r & 7;
    const float* wgt = (which ? w_en : w_st) + (long)i * (Cc * Sc);
    __shared__ float red[8];
    const int tid = threadIdx.x, lane = tid & 31, warp = tid >> 5;
    float s = 0.f;
    for (int j = tid; j < Cc * Sc; j += 256) {
        int cc = j / Sc, ss = j % Sc;
        s += mp[((long)b * Sc + ss) * Cc + cc] * wgt[j];
    }
#pragma unroll
    for (int o = 16; o; o >>= 1) s += __shfl_down_sync(0xffffffff, s, o);
    if (lane == 0) red[warp] = s;
    __syncthreads();
    if (tid == 0) {
        float t = 0.f;
#pragma unroll
        for (int w = 0; w < 8; w++) t += red[w];
        float bias = (which ? b_en : b_st)[i];
        out[PRED_SZ + which * (Bc * Sc) + b * Sc + i] = t + bias;
    }
}

// ---------------- host helpers ----------------
static inline dim3 tg(int M, int N, int batch) {
    return dim3((N + 63) / 64, (M + 63) / 64, batch);
}

static GDesc mk(const float* A, int lda, long sA1, long sA2,
                const float* B, int ldb, long sB1, long sB2,
                float* C, int ldc, long sC1, long sC2,
                int M, int N, int K, int bdiv, const float* bias, float alpha,
                int transB, int relu, int batch, int& cursor,
                int mblk = 0, long sMblk = 0)
{
    GDesc d;
    d.A = A; d.B = B; d.C = C; d.bias = bias;
    d.lda = lda; d.ldb = ldb; d.ldc = ldc;
    d.sA1 = sA1; d.sA2 = sA2; d.sB1 = sB1; d.sB2 = sB2; d.sC1 = sC1; d.sC2 = sC2;
    d.M = M; d.N = N; d.K = K; d.bdiv = bdiv;
    d.transB = transB; d.relu = relu; d.alpha = alpha;
    d.tilesX = (N + 63) / 64;
    int tilesY = (M + 63) / 64;
    d.tilesPerBatch = d.tilesX * tilesY;
    d.tileStart = cursor;
    d.mblk = mblk; d.sMblk = sMblk;
    cursor += d.tilesPerBatch * batch;
    return d;
}

extern "C" void kernel_launch(void* const* d_in, const int* in_sizes, int n_in,
                              void* d_out, int out_size)
{
    const float* vis   = (const float*)d_in[0];
    const float* query = (const float*)d_in[1];
    const int*   vlen  = (const int*)  d_in[2];
    const float* w_v1  = (const float*)d_in[3];
    const float* b_v1  = (const float*)d_in[4];
    const float* w_v2  = (const float*)d_in[5];
    const float* b_v2  = (const float*)d_in[6];
    const float* w_s1  = (const float*)d_in[7];
    const float* b_s1  = (const float*)d_in[8];
    const float* w_s2  = (const float*)d_in[9];
    const float* b_s2  = (const float*)d_in[10];
    const float* w_in  = (const float*)d_in[11];
    const float* b_in  = (const float*)d_in[12];
    const float* w_out = (const float*)d_in[13];
    const float* b_out = (const float*)d_in[14];
    const float* w_p1  = (const float*)d_in[15];
    const float* b_p1  = (const float*)d_in[16];
    const float* w_p2  = (const float*)d_in[17];
    const float* b_p2  = (const float*)d_in[18];
    const float* w_st  = (const float*)d_in[19];
    const float* b_st  = (const float*)d_in[20];
    const float* w_en  = (const float*)d_in[21];
    const float* b_en  = (const float*)d_in[22];
    float* out = (float*)d_out;

    float *xpe, *qpe, *Wc, *qbias, *qbv, *e1, *e2, *e2k, *F, *sim, *biasl,
          *cnt, *P, *W2P, *bterm, *bP, *sut, *wcoef, *Amat, *tmp,
          *qsum, *VS, *VSo, *outb, *G, *bconst, *hbuf, *mp;
    int *labels;
    cudaGetSymbolAddress((void**)&xpe,   g_xpe);
    cudaGetSymbolAddress((void**)&qpe,   g_qpe);
    cudaGetSymbolAddress((void**)&Wc,    g_Wc);
    cudaGetSymbolAddress((void**)&qbias, g_qbias);
    cudaGetSymbolAddress((void**)&qbv,   g_qbv);
    cudaGetSymbolAddress((void**)&e1,    g_e1);
    cudaGetSymbolAddress((void**)&e2,    g_e2);
    cudaGetSymbolAddress((void**)&e2k,   g_e2k);
    cudaGetSymbolAddress((void**)&F,     g_F);
    cudaGetSymbolAddress((void**)&sim,   g_sim);
    cudaGetSymbolAddress((void**)&biasl, g_biasl);
    cudaGetSymbolAddress((void**)&labels,g_labels);
    cudaGetSymbolAddress((void**)&cnt,   g_cnt);
    cudaGetSymbolAddress((void**)&P,     g_P);
    cudaGetSymbolAddress((void**)&W2P,   g_W2P);
    cudaGetSymbolAddress((void**)&bterm, g_bterm);
    cudaGetSymbolAddress((void**)&bP,    g_bP);
    cudaGetSymbolAddress((void**)&sut,   g_sut);
    cudaGetSymbolAddress((void**)&wcoef, g_wcoef);
    cudaGetSymbolAddress((void**)&Amat,  g_Amat);
    cudaGetSymbolAddress((void**)&tmp,   g_tmp);
    cudaGetSymbolAddress((void**)&qsum,  g_qsum);
    cudaGetSymbolAddress((void**)&VS,    g_VS);
    cudaGetSymbolAddress((void**)&VSo,   g_VSo);
    cudaGetSymbolAddress((void**)&outb,  g_outb);
    cudaGetSymbolAddress((void**)&G,     g_G);
    cudaGetSymbolAddress((void**)&bconst,g_bconst);
    cudaGetSymbolAddress((void**)&hbuf,  g_hbuf);
    cudaGetSymbolAddress((void**)&mp,    g_mp);

    // 1. fused positional encodings
    {
        int n = Bc * Tc * Cc + Bc * LQc * QDc;
        pe2_kernel<<<(n + 255) / 256, 256>>>(vis, query, xpe, qpe);
    }
    // 2. fused qbias + bconst; then qbv
    qb2_kernel<<<(2 * Cc * 32 + 255) / 256, 256>>>(w_v2, b_v1, b_v2,
                                                   w_p1, b_out, b_p1, qbias, bconst);
    qbv_kernel<<<(Cc * 32 + 255) / 256, 256>>>(qbias, w_in + 2L * Cc * Cc, b_in + 2 * Cc, qbv);

    // 3. G1: [Wc, e1, e2]
    {
        int cur = 0;
        GPack pk; pk.n = 3;
        pk.g[0] = mk(w_v2, Cc, 0, 0, w_v1, Cc, 0, 0, Wc, Cc, 0, 0,
                     Cc, Cc, Cc, 1, nullptr, 1.f, 0, 0, 1, cur);
        pk.g[1] = mk(qpe, QDc, 0, 0, w_s1, QDc, 0, 0, e1, Cc, 0, 0,
                     Bc * LQc, Cc, QDc, 1, b_s1, 1.f, 1, 0, 1, cur);
        pk.g[2] = mk(qpe, QDc, 0, 0, w_s2, QDc, 0, 0, e2, Cc, 0, 0,
                     Bc * LQc, Cc, QDc, 1, b_s2, 1.f, 1, 0, 1, cur);
        ggemm_kernel<<<cur, 128>>>(pk);
    }

    // 4. G2: [F = e1 @ w_v1 (NN), e2k = e2 @ wk^T + bk (TB)]
    {
        int cur = 0;
        GPack pk; pk.n = 2;
        pk.g[0] = mk(e1, Cc, 0, 0, w_v1, Cc, 0, 0, F, Cc, 0, 0,
                     Bc * LQc, Cc, Cc, 1, nullptr, 1.f, 0, 0, 1, cur);
        pk.g[1] = mk(e2, Cc, 0, 0, w_in + (long)Cc * Cc, Cc, 0, 0, e2k, Cc, 0, 0,
                     Bc * LQc, Cc, Cc, 1, b_in + Cc, 1.f, 1, 0, 1, cur);
        ggemm_kernel<<<cur, 128>>>(pk);
    }

    // 5. G3: [sim = xpe @ F^T (TB, batch 8), P = e2k_h @ wq_h (NN, batch 4)]
    {
        int cur = 0;
        GPack pk; pk.n = 2;
        pk.g[0] = mk(xpe, Cc, (long)Tc * Cc, 0, F, Cc, (long)LQc * Cc, 0,
                     sim, LQc, (long)Tc * LQc, 0,
                     Tc, LQc, Cc, 1, nullptr, 1.f, 1, 0, Bc, cur);
        pk.g[1] = mk(e2k, Cc, (long)HDc, 0, w_in, Cc, (long)HDc * Cc, 0,
                     P, Hc * Cc, (long)Cc, 0,
                     Bc * LQc, Cc, HDc, 1, nullptr, 1.f, 0, 0, Hc, cur);
        ggemm_kernel<<<cur, 128>>>(pk);
    }

    // 6. fused dots (biasl, bterm, bP)
    {
        int warps = Bc * LQc + 2 * Bc * LHc;   // 1728
        dots_kernel<<<(warps * 32 + 255) / 256, 256>>>(e1, b_v1, e2k, b_in, P, qbias,
                                                       biasl, bterm, bP);
    }

    // 7. labels ; fused mode+Amat+cnt
    argmax_kernel<<<(Bc * Tc + 255) / 256, 256>>>(sim, biasl, labels);
    amatcnt_kernel<<<Bc, 256>>>(labels, Amat, cnt);

    // 8. G4: [W2P = P_flat(768x1024) @ Wc (NN, batch 1, zero M-waste),
    //         tmp = Amat @ xpe (NN, batch 8)]
    {
        int cur = 0;
        GPack pk; pk.n = 2;
        pk.g[0] = mk(P, Cc, 0, 0, Wc, Cc, 0, 0,
                     W2P, Cc, 0, 0,
                     Bc * LHc, Cc, Cc, 1, nullptr, 1.f, 0, 0, 1, cur);
        pk.g[1] = mk(Amat, Tc, (long)LQc * Tc, 0, xpe, Cc, (long)Tc * Cc, 0,
                     tmp, Cc, (long)LQc * Cc, 0,
                     LQc, Cc, Tc, 1, nullptr, 1.f, 0, 0, Bc, cur);
        ggemm_kernel<<<cur, 128>>>(pk);
    }

    // 9. G5: [sut = xpe @ W2P^T (TB, batch 8), qsum = tmp @ Wc^T (TB)]
    {
        int cur = 0;
        GPack pk; pk.n = 2;
        pk.g[0] = mk(xpe, Cc, (long)Tc * Cc, 0, W2P, Cc, (long)LHc * Cc, 0,
                     sut, LHc, (long)Tc * LHc, 0,
                     Tc, LHc, Cc, 1, nullptr, 1.f, 1, 0, Bc, cur);
        pk.g[1] = mk(tmp, Cc, 0, 0, Wc, Cc, 0, 0, qsum, Cc, 0, 0,
                     Bc * LQc, Cc, Cc, 1, nullptr, 1.f, 1, 0, 1, cur);
        ggemm_kernel<<<cur, 128>>>(pk);
    }

    // 10. attnw (inline pooling) -> wcoef
    attnw_kernel<<<Bc * SLc, 128>>>(sut, bterm, cnt, bP, wcoef);

    // 11. VS = qsum @ wv^T ; += cnt*qbv ; VSo (TB batch 4)
    gemm_kernel<true, false><<<tg(Bc * LQc, Cc, 1), 128>>>(
        qsum, Cc, 0, 0, w_in + 2L * Cc * Cc, Cc, 0, 0, VS, Cc, 0, 0,
        Bc * LQc, Cc, Cc, 1, nullptr, 1.f);
    vsfix_kernel<<<(Bc * LQc * Cc + 255) / 256, 256>>>(VS, cnt, qbv);
    gemm_kernel<true, false><<<tg(Bc * LQc, Cc, Hc), 128>>>(
        VS, Cc, (long)HDc, 0,
        w_out, Cc, (long)HDc, 0,
        VSo, Hc * Cc, (long)Cc, 0,
        Bc * LQc, Cc, HDc, 1, nullptr, 1.f);

    // 12. G6: [G flattened M=768 batch j=4 (zero M-waste, mblk C-remap),
    //          outb = wcoef @ VSo (NN, batch 8)]
    {
        int cur = 0;
        GPack pk; pk.n = 2;
        // G row m=(b*96+r), batch z2=j: addr = G + j*(96*1024) + b*(4*96*1024) + r*1024
        pk.g[0] = mk(VSo, Cc, 0, 0,
                     w_p1, Kc * Cc, 0, (long)Cc,
                     G, Cc, 0, (long)LHc * Cc,
                     Bc * LHc, Cc, Cc, Kc, nullptr, 1.f, 1, 0, Kc, cur,
                     LHc, (long)Kc * LHc * Cc);
        pk.g[1] = mk(wcoef, LHc, (long)SLc * LHc, 0,
                     VSo, Cc, (long)LHc * Cc, 0,
                     outb, Cc, (long)SLc * Cc, 0,
                     SLc, Cc, LHc, 1, b_out, 1.f, 0, 0, Bc, cur);
        ggemm_kernel<<<cur, 128>>>(pk);
    }

    // 13. segmax (needs outb only) ; hbuf (needs G + wcoef)
    segmax_kernel<<<(Bc * Sc * Cc + 255) / 256, 256>>>(outb, vlen, mp);
    gemm_kernel<false, true><<<tg(NWc, Cc, Bc), 128>>>(
        wcoef, Kc * LHc, (long)SLc * LHc, 0,
        G, Cc, (long)Kc * LHc * Cc, 0,
        hbuf, Cc, (long)NWc * Cc, 0,
        NWc, Cc, Kc * LHc, 1, bconst, 1.f);

    // 14. heads
    pred_kernel<<<Bc * NWc, 256>>>(hbuf, w_p2, b_p2, out);
    sten_kernel<<<128, 256>>>(mp, w_st, b_st, w_en, b_en, out);
}